// round 13
// baseline (speedup 1.0000x reference)
#include <cuda_runtime.h>
#include <cuda_bf16.h>
#include <math.h>
#include <cstdint>

// Problem constants
#define BB 32
#define SS 1024
#define DIN 128
#define HH 256
#define G4H 1024          // 4*H
#define HCAT 512          // 2*H

typedef unsigned long long ull;

// ---------------- scratch (device globals; no cudaMalloc allowed) ----------
__device__ float g_xp[2u * SS * BB * G4H];        // [dir][s][b][4H]
__device__ float g_hcat0[(size_t)BB * SS * HCAT]; // [b][s][512]
__device__ float g_hcat1[(size_t)BB * SS * HCAT];
__device__ float g_ctx[(size_t)BB * SS * HCAT];
__device__ unsigned char g_hb[2][2][2][16384];    // [dir][parity][hi/lo][B-frag tile]
__device__ float g_s[BB * SS];
__device__ float g_mx[BB];
__device__ unsigned g_bar[4][32];                 // [layer*2+dir][pad] one line each

// ---------------------------------------------------------------------------
__device__ __forceinline__ float sigf(float x) { return 1.0f / (1.0f + __expf(-x)); }
__device__ __forceinline__ float tanhfast(float x) { return 1.0f - 2.0f / (__expf(2.0f * x) + 1.0f); }

__device__ __forceinline__ unsigned ld_acq(const unsigned* p) {
    unsigned v;
    asm volatile("ld.acquire.gpu.u32 %0, [%1];" : "=r"(v) : "l"(p));
    return v;
}
__device__ __forceinline__ void red_release(unsigned* p) {
    asm volatile("red.release.gpu.global.add.u32 [%0], %1;" :: "l"(p), "r"(1u) : "memory");
}
__device__ __forceinline__ void wait_ge(unsigned* p, unsigned target) {
    int hot = 2048;
    while (ld_acq(p) < target) {
        if (--hot < 0) __nanosleep(256);
    }
}

__device__ __forceinline__ uint32_t smem_u32(const void* p) {
    uint32_t a;
    asm("{ .reg .u64 tmp; cvta.to.shared.u64 tmp, %1; cvt.u32.u64 %0, tmp; }" : "=r"(a) : "l"(p));
    return a;
}
__device__ __forceinline__ void cp16(uint32_t saddr, const void* g) {
    asm volatile("cp.async.cg.shared.global [%0], [%1], 16;" :: "r"(saddr), "l"(g) : "memory");
}
#define CP_COMMIT() asm volatile("cp.async.commit_group;" ::: "memory")
#define CP_WAIT(N)  asm volatile("cp.async.wait_group %0;" :: "n"(N) : "memory")

// m16n8k16 bf16 mma, D=C in-place (fp32 accum)
__device__ __forceinline__ void mma_bf16(float* c, const uint32_t* a, const uint32_t* b) {
    asm("mma.sync.aligned.m16n8k16.row.col.f32.bf16.bf16.f32 "
        "{%0,%1,%2,%3}, {%4,%5,%6,%7}, {%8,%9}, {%0,%1,%2,%3};"
        : "+f"(c[0]), "+f"(c[1]), "+f"(c[2]), "+f"(c[3])
        : "r"(a[0]), "r"(a[1]), "r"(a[2]), "r"(a[3]), "r"(b[0]), "r"(b[1]));
}

__device__ __forceinline__ uint32_t pk(float x, float y) {
    __nv_bfloat162 t = __floats2bfloat162_rn(x, y);
    return *(uint32_t*)&t;
}
// byte offset of h[ug][n] (bf16) inside a 16KB B-fragment tile (R12 layout)
__device__ __forceinline__ uint32_t hb_off(int ug, int n) {
    int kt = ug >> 4, rem = ug & 15, low = rem & 1, k2r = rem >> 1;
    int tg = (k2r < 4) ? k2r : (k2r - 4);
    int off4 = (k2r < 4) ? 0 : 4;
    return (uint32_t)(kt * 1024 + n * 32 + tg * 8 + off4 + low * 2);
}

__global__ void reset_kernel() {
    ((unsigned*)g_bar)[threadIdx.x] = 0u;   // 128 words
}
__global__ void dummy_kernel() {}

// ---------------------------------------------------------------------------
// Tiled FP32 GEMM (unchanged): out[m,n] = sum_k A[m,k]*W[n,k] + bias[n]
// ---------------------------------------------------------------------------
template <int SRC, int EPI>
__global__ __launch_bounds__(256) void gemm_kernel(
    const float* __restrict__ A_in, int K,
    const float* __restrict__ Wf, const float* __restrict__ Wb,
    const float* __restrict__ bf, const float* __restrict__ bb,
    float* __restrict__ out_p)
{
    __shared__ float As[16][132];
    __shared__ float Bs[16][68];

    const float* A = (SRC == 0) ? A_in : (SRC == 1 ? g_hcat0 : g_ctx);

    const int t  = threadIdx.x;
    const int tx = t & 15;
    const int ty = t >> 4;
    const int m0 = blockIdx.x * 128;
    const int n0 = blockIdx.y * 64;

    const float* Wp;
    const float* biasp;
    int wrow0;
    if (EPI == 0) {
        if (n0 < 1024) { Wp = Wf; biasp = bf; wrow0 = n0; }
        else           { Wp = Wb; biasp = bb; wrow0 = n0 - 1024; }
    } else {
        Wp = Wf; biasp = bf; wrow0 = n0;
    }

    float acc[8][4];
#pragma unroll
    for (int i = 0; i < 8; i++)
#pragma unroll
        for (int j = 0; j < 4; j++) acc[i][j] = 0.0f;

    const int nkt = K >> 4;
    for (int kt = 0; kt < nkt; kt++) {
        const int k0 = kt << 4;
#pragma unroll
        for (int r = 0; r < 2; r++) {
            int idx = t + r * 256;
            int row = idx >> 2;
            int kq  = idx & 3;
            float4 v = *(const float4*)&A[(size_t)(m0 + row) * K + k0 + kq * 4];
            As[kq * 4 + 0][row] = v.x;
            As[kq * 4 + 1][row] = v.y;
            As[kq * 4 + 2][row] = v.z;
            As[kq * 4 + 3][row] = v.w;
        }
        {
            int row = t >> 2;
            int kq  = t & 3;
            float4 v = *(const float4*)&Wp[(size_t)(wrow0 + row) * K + k0 + kq * 4];
            Bs[kq * 4 + 0][row] = v.x;
            Bs[kq * 4 + 1][row] = v.y;
            Bs[kq * 4 + 2][row] = v.z;
            Bs[kq * 4 + 3][row] = v.w;
        }
        __syncthreads();
#pragma unroll
        for (int kk = 0; kk < 16; kk++) {
            float af[8], bfr[4];
            *(float4*)&af[0]  = *(const float4*)&As[kk][ty * 8];
            *(float4*)&af[4]  = *(const float4*)&As[kk][ty * 8 + 4];
            *(float4*)&bfr[0] = *(const float4*)&Bs[kk][tx * 4];
#pragma unroll
            for (int i = 0; i < 8; i++)
#pragma unroll
                for (int j = 0; j < 4; j++)
                    acc[i][j] = fmaf(af[i], bfr[j], acc[i][j]);
        }
        __syncthreads();
    }

#pragma unroll
    for (int i = 0; i < 8; i++) {
        int m = m0 + ty * 8 + i;
        int b = m >> 10;
        int s = m & 1023;
#pragma unroll
        for (int j = 0; j < 4; j++) {
            int c = tx * 4 + j;
            float v = acc[i][j] + biasp[wrow0 + c];
            if (EPI == 0) {
                int ng  = n0 + c;
                int dir = ng >> 10;
                int g   = ng & 1023;
                g_xp[((size_t)(dir * SS + s) * BB + b) * G4H + g] = v;
            } else {
                out_p[(size_t)m * 128 + (n0 + c)] = v;
            }
        }
    }
}

// ---------------------------------------------------------------------------
// Fused-direction HMMA LSTM layer. 16 CTAs, 128 threads (4 warps).
// Each CTA owns 16 hidden units of BOTH directions (M=64 gate rows per dir).
// Per step: F phase then B phase in program order — each phase's barrier
// round-trip and cp.async tile staging hide under the other phase's work.
// A fragments (hi+lo, both dirs) in smem; B tiles staged via cp.async.
// ---------------------------------------------------------------------------
#define SM_A    0                 // 2 dir x 2 hl x 4 w x 16 kt x 32 l x 16B = 128KB
#define SM_BF   131072            // f tile hi(16K)+lo(16K)
#define SM_BB   163840            // b tile hi+lo
#define SM_GATE 196608            // [64][36] floats
#define LSTM_SMEM (196608 + 9216)

__device__ __forceinline__ uint32_t a_off(int d, int hl, int w, int kt) {
    return (uint32_t)((((d * 2 + hl) * 4 + w) * 16 + kt) * 512);
}

__device__ __forceinline__ void lstm_phase(
    char* smc, int d, int slice, int t, int tcur, int pout,
    float* __restrict__ hout, float* cst)
{
    const int l = t & 31;
    const int w = t >> 5;
    float* GATE = (float*)(smc + SM_GATE);
    const char* BT = smc + (d == 0 ? SM_BF : SM_BB);
    const int au = t >> 3, ab0 = (t & 7) * 4;
    const int ug = slice * 16 + au;

    // xp prefetch (DRAM; consumed after MMA)
    float xr[4][4];
    const float* xpb = g_xp + (size_t)d * SS * BB * G4H + (size_t)tcur * BB * G4H;
#pragma unroll
    for (int G = 0; G < 4; G++) {
        int gw = G * 256 + ug;
#pragma unroll
        for (int j = 0; j < 4; j++)
            xr[G][j] = __ldcg(&xpb[(size_t)(ab0 + j) * G4H + gw]);
    }

    // MMA mainloop: 3-term bf16 split (A hi/lo from smem, B hi/lo from tile)
    float acc[4][4];
#pragma unroll
    for (int nt = 0; nt < 4; nt++)
#pragma unroll
        for (int i = 0; i < 4; i++) acc[nt][i] = 0.0f;

#pragma unroll
    for (int kt = 0; kt < 16; kt++) {
        uint4 ah = *(const uint4*)(smc + SM_A + a_off(d, 0, w, kt) + l * 16);
        uint4 al = *(const uint4*)(smc + SM_A + a_off(d, 1, w, kt) + l * 16);
        uint2 bh[4], bl[4];
#pragma unroll
        for (int nt = 0; nt < 4; nt++) {
            bh[nt] = *(const uint2*)(BT + kt * 1024 + nt * 256 + l * 8);
            bl[nt] = *(const uint2*)(BT + 16384 + kt * 1024 + nt * 256 + l * 8);
        }
#pragma unroll
        for (int nt = 0; nt < 4; nt++) {
            mma_bf16(acc[nt], (const uint32_t*)&ah, (const uint32_t*)&bh[nt]);
            mma_bf16(acc[nt], (const uint32_t*)&al, (const uint32_t*)&bh[nt]);
            mma_bf16(acc[nt], (const uint32_t*)&ah, (const uint32_t*)&bl[nt]);
        }
    }

    // epilogue -> GATE smem
    {
        const int g = l >> 2, tg = l & 3;
        float* gb = GATE + (size_t)(w * 16 + g) * 36;
#pragma unroll
        for (int nt = 0; nt < 4; nt++) {
            *(float2*)(gb + nt * 8 + tg * 2)          = make_float2(acc[nt][0], acc[nt][1]);
            *(float2*)(gb + 8 * 36 + nt * 8 + tg * 2) = make_float2(acc[nt][2], acc[nt][3]);
        }
    }
    __syncthreads();

    // activation + h stores
    {
        unsigned char* thb = g_hb[d][pout][0];
        unsigned char* tlb = g_hb[d][pout][1];
#pragma unroll
        for (int j = 0; j < 4; j++) {
            int b = ab0 + j;
            float gi = GATE[(size_t)(0 * 16 + au) * 36 + b] + xr[0][j];
            float gf = GATE[(size_t)(1 * 16 + au) * 36 + b] + xr[1][j];
            float gg = GATE[(size_t)(2 * 16 + au) * 36 + b] + xr[2][j];
            float go = GATE[(size_t)(3 * 16 + au) * 36 + b] + xr[3][j];
            float c = sigf(gf) * cst[j] + sigf(gi) * tanhfast(gg);
            cst[j] = c;
            float hv = sigf(go) * tanhfast(c);
            __nv_bfloat16 hh = __float2bfloat16(hv);
            __nv_bfloat16 hl = __float2bfloat16(hv - __bfloat162float(hh));
            uint32_t off = hb_off(ug, b);
            *(__nv_bfloat16*)(thb + off) = hh;
            *(__nv_bfloat16*)(tlb + off) = hl;
            hout[((size_t)b * SS + tcur) * HCAT + d * HH + ug] = hv;
        }
    }
}

__device__ __forceinline__ void stage_tile(char* smc, int sm_base, int d, int par, int t) {
    uint32_t sdst = smem_u32(smc + sm_base);
#pragma unroll
    for (int e = 0; e < 8; e++)
        cp16(sdst + t * 16 + e * 2048, g_hb[d][par][0] + t * 16 + e * 2048);
#pragma unroll
    for (int e = 0; e < 8; e++)
        cp16(sdst + 16384 + t * 16 + e * 2048, g_hb[d][par][1] + t * 16 + e * 2048);
}

__global__ __launch_bounds__(128, 1) void lstm_mma_kernel(
    const float* __restrict__ whf, const float* __restrict__ whb, int layer)
{
    extern __shared__ char smc[];
    const int t     = threadIdx.x;
    const int l     = t & 31;
    const int w     = t >> 5;
    const int slice = blockIdx.x;          // 0..15
    float* hout     = (layer == 0) ? g_hcat0 : g_hcat1;
    unsigned* bar_f = &g_bar[layer * 2 + 0][0];
    unsigned* bar_b = &g_bar[layer * 2 + 1][0];

    // ---- prologue: A fragments (hi+lo, both dirs) into smem ----
    {
        const int g = l >> 2, tg = l & 3;
#pragma unroll
        for (int d = 0; d < 2; d++) {
            const float* W = d ? whb : whf;
            const int grow0 = w * 256 + slice * 16 + g;
            const int grow1 = grow0 + 8;
#pragma unroll
            for (int kt = 0; kt < 16; kt++) {
                int k0 = kt * 16 + tg * 2;
                float2 p00 = *(const float2*)&W[(size_t)grow0 * HH + k0];
                float2 p08 = *(const float2*)&W[(size_t)grow0 * HH + k0 + 8];
                float2 p10 = *(const float2*)&W[(size_t)grow1 * HH + k0];
                float2 p18 = *(const float2*)&W[(size_t)grow1 * HH + k0 + 8];
                float h00x = __bfloat162float(__float2bfloat16(p00.x));
                float h00y = __bfloat162float(__float2bfloat16(p00.y));
                float h08x = __bfloat162float(__float2bfloat16(p08.x));
                float h08y = __bfloat162float(__float2bfloat16(p08.y));
                float h10x = __bfloat162float(__float2bfloat16(p10.x));
                float h10y = __bfloat162float(__float2bfloat16(p10.y));
                float h18x = __bfloat162float(__float2bfloat16(p18.x));
                float h18y = __bfloat162float(__float2bfloat16(p18.y));
                uint4 AH, AL;
                AH.x = pk(h00x, h00y);
                AH.y = pk(h10x, h10y);
                AH.z = pk(h08x, h08y);
                AH.w = pk(h18x, h18y);
                AL.x = pk(p00.x - h00x, p00.y - h00y);
                AL.y = pk(p10.x - h10x, p10.y - h10y);
                AL.z = pk(p08.x - h08x, p08.y - h08y);
                AL.w = pk(p18.x - h18x, p18.y - h18y);
                *(uint4*)(smc + SM_A + a_off(d, 0, w, kt) + l * 16) = AH;
                *(uint4*)(smc + SM_A + a_off(d, 1, w, kt) + l * 16) = AL;
            }
        }
    }

    // zero parity-0 h stripes (both dirs)
    {
        const int au = t >> 3, ab0 = (t & 7) * 4;
        const int ug = slice * 16 + au;
#pragma unroll
        for (int d = 0; d < 2; d++)
#pragma unroll
            for (int j = 0; j < 4; j++) {
                uint32_t off = hb_off(ug, ab0 + j);
                *(uint16_t*)(g_hb[d][0][0] + off) = 0;
                *(uint16_t*)(g_hb[d][0][1] + off) = 0;
            }
    }

    float cst_f[4] = {0.f, 0.f, 0.f, 0.f};
    float cst_b[4] = {0.f, 0.f, 0.f, 0.f};

    // phase-1 barrier (A smem local; h zero-init global visible)
    __syncthreads();
    if (t == 0) {
        red_release(bar_f);
        red_release(bar_b);
        wait_ge(bar_f, 16u);
        wait_ge(bar_b, 16u);
    }
    __syncthreads();

    // prologue staging: f(0) then b(0)
    stage_tile(smc, SM_BF, 0, 0, t);
    CP_COMMIT();
    stage_tile(smc, SM_BB, 1, 0, t);
    CP_COMMIT();
    CP_WAIT(1);              // f(0) done, b(0) in flight
    __syncthreads();

    for (int s = 0; s < SS; s++) {
        const int p = s & 1;

        // ===== F phase (smem_bf holds f(s)) =====
        lstm_phase(smc, 0, slice, t, s, p ^ 1, hout, cst_f);
        __syncthreads();                      // all h_f stores issued+visible order

        if (s < SS - 1) {
            if (t == 0) { red_release(bar_f); wait_ge(bar_f, 16u * (s + 2)); }
            __syncthreads();
            stage_tile(smc, SM_BF, 0, (s + 1) & 1, t);   // f(s+1), flies during B
            CP_COMMIT();
            CP_WAIT(1);                       // b(s) done (flew during F)
        } else {
            CP_WAIT(0);                       // drain b(s)
        }
        __syncthreads();

        // ===== B phase (smem_bb holds b(s)) =====
        lstm_phase(smc, 1, slice, t, SS - 1 - s, p ^ 1, hout, cst_b);
        __syncthreads();

        if (s < SS - 1) {
            if (t == 0) { red_release(bar_b); wait_ge(bar_b, 16u * (s + 2)); }
            __syncthreads();
            stage_tile(smc, SM_BB, 1, (s + 1) & 1, t);   // b(s+1), flies during next F
            CP_COMMIT();
            CP_WAIT(1);                       // f(s+1) done (flew during B)
            __syncthreads();
        }
    }
}

// ---------------------------------------------------------------------------
// attention score: s[b,t] = dot(h[b,t,:], attn_w) + attn_b ; per-b max
// ---------------------------------------------------------------------------
__global__ __launch_bounds__(256) void score_kernel(
    const float* __restrict__ attn_w, const float* __restrict__ attn_b)
{
    __shared__ float aw[HCAT];
    __shared__ float red[8];
    const int b = blockIdx.x;
    const int t = threadIdx.x;
    const int w = t >> 5, l = t & 31;
    for (int j = t; j < HCAT; j += 256) aw[j] = attn_w[j];
    __syncthreads();

    const float ab = attn_b[0];
    float mloc = -1e30f;
    for (int tt = w; tt < SS; tt += 8) {
        const float* hp = g_hcat1 + ((size_t)b * SS + tt) * HCAT;
        float sum = 0.f;
        for (int j = l; j < HCAT; j += 32) sum = fmaf(hp[j], aw[j], sum);
#pragma unroll
        for (int o = 16; o > 0; o >>= 1) sum += __shfl_xor_sync(0xFFFFFFFFu, sum, o);
        float sv = sum + ab;
        if (l == 0) g_s[b * SS + tt] = sv;
        mloc = fmaxf(mloc, sv);
    }
    if (l == 0) red[w] = mloc;
    __syncthreads();
    if (t == 0) {
        float m = red[0];
#pragma unroll
        for (int i = 1; i < 8; i++) m = fmaxf(m, red[i]);
        g_mx[b] = m;
    }
}

// ---------------------------------------------------------------------------
// cumulative softmax context: ctx[b,t,:] = cumsum(e*h)/cumsum(e)
// ---------------------------------------------------------------------------
__global__ __launch_bounds__(512) void ctx_kernel()
{
    const int b = blockIdx.x;
    const int j = threadIdx.x;
    const float mx = g_mx[b];
    float num = 0.f, den = 0.f;
    const float* sb = g_s + b * SS;
#pragma unroll 4
    for (int t = 0; t < SS; t++) {
        float e = __expf(sb[t] - mx);
        den += e;
        size_t off = ((size_t)b * SS + t) * HCAT + j;
        num = fmaf(e, __ldg(&g_hcat1[off]), num);
        g_ctx[off] = __fdividef(num, den);
    }
}

// ---------------------------------------------------------------------------
extern "C" void kernel_launch(void* const* d_in, const int* in_sizes, int n_in,
                              void* d_out, int out_size)
{
    const float* x        = (const float*)d_in[0];
    const float* w_ih_l0f = (const float*)d_in[1];
    const float* w_hh_l0f = (const float*)d_in[2];
    const float* b_l0f    = (const float*)d_in[3];
    const float* w_ih_l0b = (const float*)d_in[4];
    const float* w_hh_l0b = (const float*)d_in[5];
    const float* b_l0b    = (const float*)d_in[6];
    const float* w_ih_l1f = (const float*)d_in[7];
    const float* w_hh_l1f = (const float*)d_in[8];
    const float* b_l1f    = (const float*)d_in[9];
    const float* w_ih_l1b = (const float*)d_in[10];
    const float* w_hh_l1b = (const float*)d_in[11];
    const float* b_l1b    = (const float*)d_in[12];
    const float* attn_w   = (const float*)d_in[13];
    const float* attn_b   = (const float*)d_in[14];
    const float* head_w   = (const float*)d_in[15];
    const float* head_b   = (const float*)d_in[16];
    float* out = (float*)d_out;

    cudaFuncSetAttribute(lstm_mma_kernel, cudaFuncAttributeMaxDynamicSharedMemorySize, LSTM_SMEM);

    reset_kernel<<<1, 128>>>();                                   // idx 0

    // layer 0: projection + recurrence (dummy shifts lstm0 into ncu slot 3)
    gemm_kernel<0, 0><<<dim3(256, 32), 256>>>(x, DIN, w_ih_l0f, w_ih_l0b, b_l0f, b_l0b, nullptr);   // idx 1
    dummy_kernel<<<1, 32>>>();                                    // idx 2
    lstm_mma_kernel<<<16, 128, LSTM_SMEM>>>(w_hh_l0f, w_hh_l0b, 0);  // idx 3 <- profiled
    // layer 1: projection (A = g_hcat0) + recurrence
    gemm_kernel<1, 0><<<dim3(256, 32), 256>>>(nullptr, HCAT, w_ih_l1f, w_ih_l1b, b_l1f, b_l1b, nullptr);
    lstm_mma_kernel<<<16, 128, LSTM_SMEM>>>(w_hh_l1f, w_hh_l1b, 1);

    // attention + context + head
    score_kernel<<<32, 256>>>(attn_w, attn_b);
    ctx_kernel<<<32, 512>>>();
    gemm_kernel<2, 1><<<dim3(256, 2), 256>>>(nullptr, HCAT, head_w, nullptr, head_b, nullptr, out);
}

// round 14
// speedup vs baseline: 2.0144x; 2.0144x over previous
#include <cuda_runtime.h>
#include <cuda_bf16.h>
#include <math.h>
#include <cstdint>

// Problem constants
#define BB 32
#define SS 1024
#define DIN 128
#define HH 256
#define G4H 1024          // 4*H
#define HCAT 512          // 2*H

typedef unsigned long long ull;

// ---------------- scratch (device globals; no cudaMalloc allowed) ----------
__device__ float g_xp[2u * SS * BB * G4H];        // [dir][s][b][4H]
__device__ float g_hcat0[(size_t)BB * SS * HCAT]; // [b][s][512]
__device__ float g_hcat1[(size_t)BB * SS * HCAT];
__device__ float g_ctx[(size_t)BB * SS * HCAT];
__device__ unsigned char g_hb[2][2][2][16384];    // [dir][parity][hi/lo][B-frag tile]
__device__ float g_s[BB * SS];
__device__ float g_mx[BB];
__device__ unsigned g_bar[4][32];                 // [layer*2+dir][pad] one line each

// ---------------------------------------------------------------------------
__device__ __forceinline__ float sigf(float x) { return 1.0f / (1.0f + __expf(-x)); }
__device__ __forceinline__ float tanhfast(float x) { return 1.0f - 2.0f / (__expf(2.0f * x) + 1.0f); }

__device__ __forceinline__ unsigned ld_acq(const unsigned* p) {
    unsigned v;
    asm volatile("ld.acquire.gpu.u32 %0, [%1];" : "=r"(v) : "l"(p));
    return v;
}
__device__ __forceinline__ void red_release(unsigned* p) {
    asm volatile("red.release.gpu.global.add.u32 [%0], %1;" :: "l"(p), "r"(1u) : "memory");
}
__device__ __forceinline__ void wait_ge(unsigned* p, unsigned target) {
    int hot = 2048;
    while (ld_acq(p) < target) {
        if (--hot < 0) __nanosleep(256);
    }
}

// m16n8k16 bf16 mma, D=C in-place (fp32 accum)
__device__ __forceinline__ void mma_bf16(float* c, const uint32_t* a, const uint32_t* b) {
    asm("mma.sync.aligned.m16n8k16.row.col.f32.bf16.bf16.f32 "
        "{%0,%1,%2,%3}, {%4,%5,%6,%7}, {%8,%9}, {%0,%1,%2,%3};"
        : "+f"(c[0]), "+f"(c[1]), "+f"(c[2]), "+f"(c[3])
        : "r"(a[0]), "r"(a[1]), "r"(a[2]), "r"(a[3]), "r"(b[0]), "r"(b[1]));
}

__device__ __forceinline__ uint32_t pk(float x, float y) {
    __nv_bfloat162 t = __floats2bfloat162_rn(x, y);
    return *(uint32_t*)&t;
}
// byte offset of h[ug][n] (bf16) inside a 16KB B-frag tile (R12 layout)
__device__ __forceinline__ uint32_t hb_off(int ug, int n) {
    int kt = ug >> 4, rem = ug & 15, low = rem & 1, k2r = rem >> 1;
    int tg = (k2r < 4) ? k2r : (k2r - 4);
    int off4 = (k2r < 4) ? 0 : 4;
    return (uint32_t)(kt * 1024 + n * 32 + tg * 8 + off4 + low * 2);
}

__global__ void reset_kernel() {
    ((unsigned*)g_bar)[threadIdx.x] = 0u;   // 128 words
}
__global__ void dummy_kernel() {}

// ---------------------------------------------------------------------------
// bf16 HMMA projection GEMM: g_xp[..] = A[m,:] . W[n,:] + bias[n]
// BM=64, BN=64, BK=32, 128 threads (4 warps), 3-term bf16 hi/lo split.
// SRC: 0 = A param (x, K=128), 1 = g_hcat0 (K=512).
// ---------------------------------------------------------------------------
template <int SRC>
__global__ __launch_bounds__(128) void proj_mma_kernel(
    const float* __restrict__ A_in, int KD,
    const float* __restrict__ Wf, const float* __restrict__ Wb,
    const float* __restrict__ bf, const float* __restrict__ bb)
{
    __shared__ char sm[16384];     // AH 4K | AL 4K | BH 4K | BL 4K

    const float* A = (SRC == 0) ? A_in : g_hcat0;
    const int t = threadIdx.x;
    const int l = t & 31;
    const int w = t >> 5;
    const int m0 = blockIdx.x * 64;
    const int n0 = blockIdx.y * 64;

    const float* Wp;
    const float* biasp;
    int wrow0;
    if (n0 < 1024) { Wp = Wf; biasp = bf; wrow0 = n0; }
    else           { Wp = Wb; biasp = bb; wrow0 = n0 - 1024; }

    float acc[8][4];
#pragma unroll
    for (int nt = 0; nt < 8; nt++)
#pragma unroll
        for (int i = 0; i < 4; i++) acc[nt][i] = 0.0f;

    const int niter = KD >> 5;
    for (int it = 0; it < niter; it++) {
        const int k0 = it << 5;
        // ---- stage A (64 rows x 32 k) as hi/lo mma fragments ----
#pragma unroll
        for (int ee = 0; ee < 8; ee++) {
            int e = t + ee * 128;
            int r = e >> 4, p = e & 15;
            float2 v = *(const float2*)&A[(size_t)(m0 + r) * KD + k0 + 2 * p];
            float hx = __bfloat162float(__float2bfloat16(v.x));
            float hy = __bfloat162float(__float2bfloat16(v.y));
            uint32_t hi = pk(hx, hy);
            uint32_t lo = pk(v.x - hx, v.y - hy);
            int rr = r & 15;
            uint32_t off = (uint32_t)((r >> 4) * 2 + (p >> 3)) * 512
                         + (uint32_t)((rr & 7) * 4 + (p & 3)) * 16
                         + (uint32_t)((rr >> 3) + ((p >> 2) & 1) * 2) * 4;
            *(uint32_t*)(sm + off)        = hi;
            *(uint32_t*)(sm + 4096 + off) = lo;
        }
        // ---- stage B (64 cols x 32 k) as hi/lo mma fragments ----
#pragma unroll
        for (int ee = 0; ee < 8; ee++) {
            int e = t + ee * 128;
            int c = e >> 4, p = e & 15;
            float2 v = *(const float2*)&Wp[(size_t)(wrow0 + c) * KD + k0 + 2 * p];
            float hx = __bfloat162float(__float2bfloat16(v.x));
            float hy = __bfloat162float(__float2bfloat16(v.y));
            uint32_t hi = pk(hx, hy);
            uint32_t lo = pk(v.x - hx, v.y - hy);
            uint32_t off = (uint32_t)(p >> 3) * 2048
                         + (uint32_t)(c >> 3) * 256
                         + (uint32_t)((c & 7) * 4 + (p & 3)) * 8
                         + (uint32_t)((p >> 2) & 1) * 4;
            *(uint32_t*)(sm + 8192 + off)  = hi;
            *(uint32_t*)(sm + 12288 + off) = lo;
        }
        __syncthreads();
        // ---- mma: 2 ktiles x 8 ntiles x 3 terms ----
#pragma unroll
        for (int kt = 0; kt < 2; kt++) {
            uint4 ah = *(const uint4*)(sm + (w * 2 + kt) * 512 + l * 16);
            uint4 al = *(const uint4*)(sm + 4096 + (w * 2 + kt) * 512 + l * 16);
#pragma unroll
            for (int nt = 0; nt < 8; nt++) {
                uint2 bh = *(const uint2*)(sm + 8192 + kt * 2048 + nt * 256 + l * 8);
                uint2 bl = *(const uint2*)(sm + 12288 + kt * 2048 + nt * 256 + l * 8);
                mma_bf16(acc[nt], (const uint32_t*)&ah, (const uint32_t*)&bh);
                mma_bf16(acc[nt], (const uint32_t*)&al, (const uint32_t*)&bh);
                mma_bf16(acc[nt], (const uint32_t*)&ah, (const uint32_t*)&bl);
            }
        }
        __syncthreads();
    }

    // ---- epilogue: bias + scatter to g_xp[dir][s][b][4H] ----
    const int r0 = m0 + w * 16 + (l >> 2);
#pragma unroll
    for (int nt = 0; nt < 8; nt++) {
        int cl = wrow0 + nt * 8 + (l & 3) * 2;     // dir-local col
        float b0v = biasp[cl];
        float b1v = biasp[cl + 1];
        int ng  = n0 + nt * 8 + (l & 3) * 2;
        int dir = ng >> 10;
        int g   = ng & 1023;
        {
            int m = r0, b = m >> 10, s = m & 1023;
            size_t base = ((size_t)(dir * SS + s) * BB + b) * G4H;
            g_xp[base + g]     = acc[nt][0] + b0v;
            g_xp[base + g + 1] = acc[nt][1] + b1v;
        }
        {
            int m = r0 + 8, b = m >> 10, s = m & 1023;
            size_t base = ((size_t)(dir * SS + s) * BB + b) * G4H;
            g_xp[base + g]     = acc[nt][2] + b0v;
            g_xp[base + g + 1] = acc[nt][3] + b1v;
        }
    }
}

// ---------------------------------------------------------------------------
// Tiled FP32 GEMM (head only): out[m,n] = sum_k A[m,k]*W[n,k] + bias[n]
// ---------------------------------------------------------------------------
__global__ __launch_bounds__(256) void head_gemm_kernel(
    int K, const float* __restrict__ Wf, const float* __restrict__ bf,
    float* __restrict__ out_p)
{
    __shared__ float As[16][132];
    __shared__ float Bs[16][68];

    const float* A = g_ctx;
    const int t  = threadIdx.x;
    const int tx = t & 15;
    const int ty = t >> 4;
    const int m0 = blockIdx.x * 128;
    const int n0 = blockIdx.y * 64;
    const float* Wp = Wf;
    const float* biasp = bf;
    const int wrow0 = n0;

    float acc[8][4];
#pragma unroll
    for (int i = 0; i < 8; i++)
#pragma unroll
        for (int j = 0; j < 4; j++) acc[i][j] = 0.0f;

    const int nkt = K >> 4;
    for (int kt = 0; kt < nkt; kt++) {
        const int k0 = kt << 4;
#pragma unroll
        for (int r = 0; r < 2; r++) {
            int idx = t + r * 256;
            int row = idx >> 2;
            int kq  = idx & 3;
            float4 v = *(const float4*)&A[(size_t)(m0 + row) * K + k0 + kq * 4];
            As[kq * 4 + 0][row] = v.x;
            As[kq * 4 + 1][row] = v.y;
            As[kq * 4 + 2][row] = v.z;
            As[kq * 4 + 3][row] = v.w;
        }
        {
            int row = t >> 2;
            int kq  = t & 3;
            float4 v = *(const float4*)&Wp[(size_t)(wrow0 + row) * K + k0 + kq * 4];
            Bs[kq * 4 + 0][row] = v.x;
            Bs[kq * 4 + 1][row] = v.y;
            Bs[kq * 4 + 2][row] = v.z;
            Bs[kq * 4 + 3][row] = v.w;
        }
        __syncthreads();
#pragma unroll
        for (int kk = 0; kk < 16; kk++) {
            float af[8], bfr[4];
            *(float4*)&af[0]  = *(const float4*)&As[kk][ty * 8];
            *(float4*)&af[4]  = *(const float4*)&As[kk][ty * 8 + 4];
            *(float4*)&bfr[0] = *(const float4*)&Bs[kk][tx * 4];
#pragma unroll
            for (int i = 0; i < 8; i++)
#pragma unroll
                for (int j = 0; j < 4; j++)
                    acc[i][j] = fmaf(af[i], bfr[j], acc[i][j]);
        }
        __syncthreads();
    }

#pragma unroll
    for (int i = 0; i < 8; i++) {
        int m = m0 + ty * 8 + i;
#pragma unroll
        for (int j = 0; j < 4; j++) {
            int c = tx * 4 + j;
            out_p[(size_t)m * 128 + (n0 + c)] = acc[i][j] + biasp[wrow0 + c];
        }
    }
}

// ---------------------------------------------------------------------------
// HMMA bidirectional LSTM layer (R12, unchanged). 32 CTAs (16/dir), 128 thr.
// ---------------------------------------------------------------------------
#define SM_BHI 0
#define SM_BLO 16384
#define SM_ALO 32768          // 32KB: [w][kt][pair][lane] 8B chunks
#define SM_GATE 65536         // [64 rows][36] floats
#define LSTM_SMEM (65536 + 64 * 36 * 4)

__global__ __launch_bounds__(128, 1) void lstm_mma_kernel(
    const float* __restrict__ whf, const float* __restrict__ whb, int layer)
{
    extern __shared__ char smc[];
    float* GATE = (float*)(smc + SM_GATE);

    const int t     = threadIdx.x;
    const int l     = t & 31;
    const int w     = t >> 5;             // warp = gate
    const int dir   = blockIdx.x >> 4;
    const int slice = blockIdx.x & 15;
    const float* W  = dir ? whb : whf;
    float* hout     = (layer == 0) ? g_hcat0 : g_hcat1;
    unsigned* bar   = &g_bar[layer * 2 + dir][0];

    const int g  = l >> 2;                // 0..7
    const int tg = l & 3;                 // 0..3
    const int grow0 = w * 256 + slice * 16 + g;
    const int grow1 = grow0 + 8;

    // ---- one-time: W fragments (hi in regs, lo to smem) ----
    uint32_t Ahi[16][4];
#pragma unroll
    for (int kt = 0; kt < 16; kt++) {
        int k0 = kt * 16 + tg * 2;
        float2 p00 = *(const float2*)&W[(size_t)grow0 * HH + k0];
        float2 p08 = *(const float2*)&W[(size_t)grow0 * HH + k0 + 8];
        float2 p10 = *(const float2*)&W[(size_t)grow1 * HH + k0];
        float2 p18 = *(const float2*)&W[(size_t)grow1 * HH + k0 + 8];
        float h00x = __bfloat162float(__float2bfloat16(p00.x));
        float h00y = __bfloat162float(__float2bfloat16(p00.y));
        float h08x = __bfloat162float(__float2bfloat16(p08.x));
        float h08y = __bfloat162float(__float2bfloat16(p08.y));
        float h10x = __bfloat162float(__float2bfloat16(p10.x));
        float h10y = __bfloat162float(__float2bfloat16(p10.y));
        float h18x = __bfloat162float(__float2bfloat16(p18.x));
        float h18y = __bfloat162float(__float2bfloat16(p18.y));
        Ahi[kt][0] = pk(h00x, h00y);
        Ahi[kt][1] = pk(h10x, h10y);
        Ahi[kt][2] = pk(h08x, h08y);
        Ahi[kt][3] = pk(h18x, h18y);
        uint2 lo1, lo2;
        lo1.x = pk(p00.x - h00x, p00.y - h00y);
        lo1.y = pk(p08.x - h08x, p08.y - h08y);
        lo2.x = pk(p10.x - h10x, p10.y - h10y);
        lo2.y = pk(p18.x - h18x, p18.y - h18y);
        *(uint2*)(smc + SM_ALO + (w * 16 + kt) * 512 + l * 8)       = lo1;
        *(uint2*)(smc + SM_ALO + (w * 16 + kt) * 512 + 256 + l * 8) = lo2;
    }

    // activation mapping: u = t>>3 (0..15), batches (t&7)*4 .. +3
    const int au  = t >> 3;
    const int ab0 = (t & 7) * 4;
    const int ug  = slice * 16 + au;
    float cst[4] = {0.f, 0.f, 0.f, 0.f};

    // zero parity-0 h stripe (hi+lo)
#pragma unroll
    for (int j = 0; j < 4; j++) {
        uint32_t off = hb_off(ug, ab0 + j);
        *(uint16_t*)(g_hb[dir][0][0] + off) = 0;
        *(uint16_t*)(g_hb[dir][0][1] + off) = 0;
    }

    // phase-1 barrier (init + Alo smem visible)
    unsigned phase = 1;
    __syncthreads();
    if (t == 0) { red_release(bar); wait_ge(bar, 16u * phase); }
    __syncthreads();

    const float* xpd = g_xp + (size_t)dir * SS * BB * G4H;

    for (int s = 0; s < SS; s++) {
        const int p    = s & 1;
        const int tcur = dir ? (SS - 1 - s) : s;

        // prefetch xp for my 4 gates x 4 batches
        float xr[4][4];
        {
            const float* xpb = xpd + (size_t)tcur * BB * G4H;
#pragma unroll
            for (int G = 0; G < 4; G++) {
                int gw = G * 256 + slice * 16 + au;
#pragma unroll
                for (int j = 0; j < 4; j++)
                    xr[G][j] = __ldcg(&xpb[(size_t)(ab0 + j) * G4H + gw]);
            }
        }

        // stage h B-frag tiles (hi+lo, 16KB each): straight float4 copy
        {
            const float4* shi = (const float4*)g_hb[dir][p][0];
            const float4* slo = (const float4*)g_hb[dir][p][1];
            float4* dhi = (float4*)(smc + SM_BHI);
            float4* dlo = (float4*)(smc + SM_BLO);
#pragma unroll
            for (int e = 0; e < 8; e++) {
                dhi[t + e * 128] = __ldcg(shi + t + e * 128);
                dlo[t + e * 128] = __ldcg(slo + t + e * 128);
            }
        }
        __syncthreads();

        // MMA mainloop: 3-term bf16 split
        float acc[4][4];
#pragma unroll
        for (int nt = 0; nt < 4; nt++)
#pragma unroll
            for (int i = 0; i < 4; i++) acc[nt][i] = 0.0f;

#pragma unroll
        for (int kt = 0; kt < 16; kt++) {
            uint2 bh[4], bl[4];
#pragma unroll
            for (int nt = 0; nt < 4; nt++) {
                bh[nt] = *(const uint2*)(smc + SM_BHI + kt * 1024 + nt * 256 + l * 8);
                bl[nt] = *(const uint2*)(smc + SM_BLO + kt * 1024 + nt * 256 + l * 8);
            }
            uint2 al1 = *(const uint2*)(smc + SM_ALO + (w * 16 + kt) * 512 + l * 8);
            uint2 al2 = *(const uint2*)(smc + SM_ALO + (w * 16 + kt) * 512 + 256 + l * 8);
            uint32_t alo[4] = {al1.x, al2.x, al1.y, al2.y};
#pragma unroll
            for (int nt = 0; nt < 4; nt++) {
                mma_bf16(acc[nt], Ahi[kt], (const uint32_t*)&bh[nt]);
                mma_bf16(acc[nt], alo,     (const uint32_t*)&bh[nt]);
                mma_bf16(acc[nt], Ahi[kt], (const uint32_t*)&bl[nt]);
            }
        }

        // epilogue: D -> GATE smem [row m][n]
        {
            float* gb = GATE + (size_t)(w * 16 + g) * 36;
#pragma unroll
            for (int nt = 0; nt < 4; nt++) {
                *(float2*)(gb + nt * 8 + tg * 2)          = make_float2(acc[nt][0], acc[nt][1]);
                *(float2*)(gb + 8 * 36 + nt * 8 + tg * 2) = make_float2(acc[nt][2], acc[nt][3]);
            }
        }
        __syncthreads();

        // activation
        {
            unsigned char* thb = g_hb[dir][p ^ 1][0];
            unsigned char* tlb = g_hb[dir][p ^ 1][1];
#pragma unroll
            for (int j = 0; j < 4; j++) {
                int b = ab0 + j;
                float gi = GATE[(size_t)(0 * 16 + au) * 36 + b] + xr[0][j];
                float gf = GATE[(size_t)(1 * 16 + au) * 36 + b] + xr[1][j];
                float gg = GATE[(size_t)(2 * 16 + au) * 36 + b] + xr[2][j];
                float go = GATE[(size_t)(3 * 16 + au) * 36 + b] + xr[3][j];
                float c = sigf(gf) * cst[j] + sigf(gi) * tanhfast(gg);
                cst[j] = c;
                float hv = sigf(go) * tanhfast(c);
                __nv_bfloat16 hh = __float2bfloat16(hv);
                __nv_bfloat16 hl = __float2bfloat16(hv - __bfloat162float(hh));
                uint32_t off = hb_off(ug, b);
                *(__nv_bfloat16*)(thb + off) = hh;
                *(__nv_bfloat16*)(tlb + off) = hl;
                hout[((size_t)b * SS + tcur) * HCAT + dir * HH + ug] = hv;
            }
        }

        if (s == SS - 1) break;

        // per-direction counter barrier (16 arrivals, red.release)
        phase++;
        __syncthreads();
        if (t == 0) { red_release(bar); wait_ge(bar, 16u * phase); }
        __syncthreads();
    }
}

// ---------------------------------------------------------------------------
// attention score: s[b,t] = dot(h[b,t,:], attn_w) + attn_b ; per-b max
// ---------------------------------------------------------------------------
__global__ __launch_bounds__(256) void score_kernel(
    const float* __restrict__ attn_w, const float* __restrict__ attn_b)
{
    __shared__ float aw[HCAT];
    __shared__ float red[8];
    const int b = blockIdx.x;
    const int t = threadIdx.x;
    const int w = t >> 5, l = t & 31;
    for (int j = t; j < HCAT; j += 256) aw[j] = attn_w[j];
    __syncthreads();

    const float ab = attn_b[0];
    float mloc = -1e30f;
    for (int tt = w; tt < SS; tt += 8) {
        const float* hp = g_hcat1 + ((size_t)b * SS + tt) * HCAT;
        float sum = 0.f;
        for (int j = l; j < HCAT; j += 32) sum = fmaf(hp[j], aw[j], sum);
#pragma unroll
        for (int o = 16; o > 0; o >>= 1) sum += __shfl_xor_sync(0xFFFFFFFFu, sum, o);
        float sv = sum + ab;
        if (l == 0) g_s[b * SS + tt] = sv;
        mloc = fmaxf(mloc, sv);
    }
    if (l == 0) red[w] = mloc;
    __syncthreads();
    if (t == 0) {
        float m = red[0];
#pragma unroll
        for (int i = 1; i < 8; i++) m = fmaxf(m, red[i]);
        g_mx[b] = m;
    }
}

// ---------------------------------------------------------------------------
// cumulative softmax context: ctx[b,t,:] = cumsum(e*h)/cumsum(e)
// ---------------------------------------------------------------------------
__global__ __launch_bounds__(512) void ctx_kernel()
{
    const int b = blockIdx.x;
    const int j = threadIdx.x;
    const float mx = g_mx[b];
    float num = 0.f, den = 0.f;
    const float* sb = g_s + b * SS;
#pragma unroll 4
    for (int t = 0; t < SS; t++) {
        float e = __expf(sb[t] - mx);
        den += e;
        size_t off = ((size_t)b * SS + t) * HCAT + j;
        num = fmaf(e, __ldg(&g_hcat1[off]), num);
        g_ctx[off] = __fdividef(num, den);
    }
}

// ---------------------------------------------------------------------------
extern "C" void kernel_launch(void* const* d_in, const int* in_sizes, int n_in,
                              void* d_out, int out_size)
{
    const float* x        = (const float*)d_in[0];
    const float* w_ih_l0f = (const float*)d_in[1];
    const float* w_hh_l0f = (const float*)d_in[2];
    const float* b_l0f    = (const float*)d_in[3];
    const float* w_ih_l0b = (const float*)d_in[4];
    const float* w_hh_l0b = (const float*)d_in[5];
    const float* b_l0b    = (const float*)d_in[6];
    const float* w_ih_l1f = (const float*)d_in[7];
    const float* w_hh_l1f = (const float*)d_in[8];
    const float* b_l1f    = (const float*)d_in[9];
    const float* w_ih_l1b = (const float*)d_in[10];
    const float* w_hh_l1b = (const float*)d_in[11];
    const float* b_l1b    = (const float*)d_in[12];
    const float* attn_w   = (const float*)d_in[13];
    const float* attn_b   = (const float*)d_in[14];
    const float* head_w   = (const float*)d_in[15];
    const float* head_b   = (const float*)d_in[16];
    float* out = (float*)d_out;

    cudaFuncSetAttribute(lstm_mma_kernel, cudaFuncAttributeMaxDynamicSharedMemorySize, LSTM_SMEM);

    reset_kernel<<<1, 128>>>();                                   // idx 0

    // layer 0: bf16 HMMA projection + recurrence (lstm0 in ncu slot 3)
    proj_mma_kernel<0><<<dim3(512, 32), 128>>>(x, DIN, w_ih_l0f, w_ih_l0b, b_l0f, b_l0b);   // idx 1
    dummy_kernel<<<1, 32>>>();                                    // idx 2
    lstm_mma_kernel<<<32, 128, LSTM_SMEM>>>(w_hh_l0f, w_hh_l0b, 0);  // idx 3 <- profiled
    // layer 1: bf16 HMMA projection + recurrence
    proj_mma_kernel<1><<<dim3(512, 32), 128>>>(nullptr, HCAT, w_ih_l1f, w_ih_l1b, b_l1f, b_l1b);
    lstm_mma_kernel<<<32, 128, LSTM_SMEM>>>(w_hh_l1f, w_hh_l1b, 1);

    // attention + context + head
    score_kernel<<<32, 256>>>(attn_w, attn_b);
    ctx_kernel<<<32, 512>>>();
    head_gemm_kernel<<<dim3(256, 2), 256>>>(HCAT, head_w, head_b, out);
}

// round 15
// speedup vs baseline: 2.0514x; 1.0184x over previous
#include <cuda_runtime.h>
#include <cuda_bf16.h>
#include <math.h>
#include <cstdint>

// Problem constants
#define BB 32
#define SS 1024
#define DIN 128
#define HH 256
#define G4H 1024          // 4*H
#define HCAT 512          // 2*H

typedef unsigned long long ull;

// ---------------- scratch (device globals; no cudaMalloc allowed) ----------
__device__ float g_xp[2u * SS * BB * G4H];        // [dir][s][b][4H]
__device__ float g_hcat0[(size_t)BB * SS * HCAT]; // [b][s][512]
__device__ float g_hcat1[(size_t)BB * SS * HCAT];
__device__ float g_ctx[(size_t)BB * SS * HCAT];
__device__ unsigned char g_hb[2][2][2][16384];    // [dir][parity][hi/lo][B-frag tile]
__device__ float g_s[BB * SS];
__device__ float g_mx[BB];
__device__ unsigned g_bar[4][32];                 // [layer*2+dir][pad] one line each

// ---------------------------------------------------------------------------
__device__ __forceinline__ float sigf(float x) { return 1.0f / (1.0f + __expf(-x)); }
__device__ __forceinline__ float tanhfast(float x) { return 1.0f - 2.0f / (__expf(2.0f * x) + 1.0f); }

__device__ __forceinline__ unsigned ld_acq(const unsigned* p) {
    unsigned v;
    asm volatile("ld.acquire.gpu.u32 %0, [%1];" : "=r"(v) : "l"(p));
    return v;
}
__device__ __forceinline__ void red_release(unsigned* p) {
    asm volatile("red.release.gpu.global.add.u32 [%0], %1;" :: "l"(p), "r"(1u) : "memory");
}
__device__ __forceinline__ void wait_ge(unsigned* p, unsigned target) {
    int hot = 2048;
    while (ld_acq(p) < target) {
        if (--hot < 0) __nanosleep(256);
    }
}

// m16n8k16 bf16 mma, D=C in-place (fp32 accum)
__device__ __forceinline__ void mma_bf16(float* c, const uint32_t* a, const uint32_t* b) {
    asm("mma.sync.aligned.m16n8k16.row.col.f32.bf16.bf16.f32 "
        "{%0,%1,%2,%3}, {%4,%5,%6,%7}, {%8,%9}, {%0,%1,%2,%3};"
        : "+f"(c[0]), "+f"(c[1]), "+f"(c[2]), "+f"(c[3])
        : "r"(a[0]), "r"(a[1]), "r"(a[2]), "r"(a[3]), "r"(b[0]), "r"(b[1]));
}

__device__ __forceinline__ uint32_t pk(float x, float y) {
    __nv_bfloat162 t = __floats2bfloat162_rn(x, y);
    return *(uint32_t*)&t;
}
// byte offset of h[ug][n] (bf16) inside a 16KB B-frag tile (R12 layout)
__device__ __forceinline__ uint32_t hb_off(int ug, int n) {
    int kt = ug >> 4, rem = ug & 15, low = rem & 1, k2r = rem >> 1;
    int tg = (k2r < 4) ? k2r : (k2r - 4);
    int off4 = (k2r < 4) ? 0 : 4;
    return (uint32_t)(kt * 1024 + n * 32 + tg * 8 + off4 + low * 2);
}

__device__ __forceinline__ uint2 ldcg_u2(const void* p) {
    uint2 v;
    asm volatile("ld.global.cg.v2.u32 {%0,%1}, [%2];" : "=r"(v.x), "=r"(v.y) : "l"(p));
    return v;
}

__global__ void reset_kernel() {
    ((unsigned*)g_bar)[threadIdx.x] = 0u;   // 128 words
}
__global__ void dummy_kernel() {}

// ---------------------------------------------------------------------------
// bf16 HMMA projection GEMM (R14, unchanged): g_xp = A.W^T + bias
// ---------------------------------------------------------------------------
template <int SRC>
__global__ __launch_bounds__(128) void proj_mma_kernel(
    const float* __restrict__ A_in, int KD,
    const float* __restrict__ Wf, const float* __restrict__ Wb,
    const float* __restrict__ bf, const float* __restrict__ bb)
{
    __shared__ char sm[16384];     // AH 4K | AL 4K | BH 4K | BL 4K

    const float* A = (SRC == 0) ? A_in : g_hcat0;
    const int t = threadIdx.x;
    const int l = t & 31;
    const int w = t >> 5;
    const int m0 = blockIdx.x * 64;
    const int n0 = blockIdx.y * 64;

    const float* Wp;
    const float* biasp;
    int wrow0;
    if (n0 < 1024) { Wp = Wf; biasp = bf; wrow0 = n0; }
    else           { Wp = Wb; biasp = bb; wrow0 = n0 - 1024; }

    float acc[8][4];
#pragma unroll
    for (int nt = 0; nt < 8; nt++)
#pragma unroll
        for (int i = 0; i < 4; i++) acc[nt][i] = 0.0f;

    const int niter = KD >> 5;
    for (int it = 0; it < niter; it++) {
        const int k0 = it << 5;
#pragma unroll
        for (int ee = 0; ee < 8; ee++) {
            int e = t + ee * 128;
            int r = e >> 4, p = e & 15;
            float2 v = *(const float2*)&A[(size_t)(m0 + r) * KD + k0 + 2 * p];
            float hx = __bfloat162float(__float2bfloat16(v.x));
            float hy = __bfloat162float(__float2bfloat16(v.y));
            uint32_t hi = pk(hx, hy);
            uint32_t lo = pk(v.x - hx, v.y - hy);
            int rr = r & 15;
            uint32_t off = (uint32_t)((r >> 4) * 2 + (p >> 3)) * 512
                         + (uint32_t)((rr & 7) * 4 + (p & 3)) * 16
                         + (uint32_t)((rr >> 3) + ((p >> 2) & 1) * 2) * 4;
            *(uint32_t*)(sm + off)        = hi;
            *(uint32_t*)(sm + 4096 + off) = lo;
        }
#pragma unroll
        for (int ee = 0; ee < 8; ee++) {
            int e = t + ee * 128;
            int c = e >> 4, p = e & 15;
            float2 v = *(const float2*)&Wp[(size_t)(wrow0 + c) * KD + k0 + 2 * p];
            float hx = __bfloat162float(__float2bfloat16(v.x));
            float hy = __bfloat162float(__float2bfloat16(v.y));
            uint32_t hi = pk(hx, hy);
            uint32_t lo = pk(v.x - hx, v.y - hy);
            uint32_t off = (uint32_t)(p >> 3) * 2048
                         + (uint32_t)(c >> 3) * 256
                         + (uint32_t)((c & 7) * 4 + (p & 3)) * 8
                         + (uint32_t)((p >> 2) & 1) * 4;
            *(uint32_t*)(sm + 8192 + off)  = hi;
            *(uint32_t*)(sm + 12288 + off) = lo;
        }
        __syncthreads();
#pragma unroll
        for (int kt = 0; kt < 2; kt++) {
            uint4 ah = *(const uint4*)(sm + (w * 2 + kt) * 512 + l * 16);
            uint4 al = *(const uint4*)(sm + 4096 + (w * 2 + kt) * 512 + l * 16);
#pragma unroll
            for (int nt = 0; nt < 8; nt++) {
                uint2 bh = *(const uint2*)(sm + 8192 + kt * 2048 + nt * 256 + l * 8);
                uint2 bl = *(const uint2*)(sm + 12288 + kt * 2048 + nt * 256 + l * 8);
                mma_bf16(acc[nt], (const uint32_t*)&ah, (const uint32_t*)&bh);
                mma_bf16(acc[nt], (const uint32_t*)&al, (const uint32_t*)&bh);
                mma_bf16(acc[nt], (const uint32_t*)&ah, (const uint32_t*)&bl);
            }
        }
        __syncthreads();
    }

    const int r0 = m0 + w * 16 + (l >> 2);
#pragma unroll
    for (int nt = 0; nt < 8; nt++) {
        int cl = wrow0 + nt * 8 + (l & 3) * 2;
        float b0v = biasp[cl];
        float b1v = biasp[cl + 1];
        int ng  = n0 + nt * 8 + (l & 3) * 2;
        int dir = ng >> 10;
        int g   = ng & 1023;
        {
            int m = r0, b = m >> 10, s = m & 1023;
            size_t base = ((size_t)(dir * SS + s) * BB + b) * G4H;
            g_xp[base + g]     = acc[nt][0] + b0v;
            g_xp[base + g + 1] = acc[nt][1] + b1v;
        }
        {
            int m = r0 + 8, b = m >> 10, s = m & 1023;
            size_t base = ((size_t)(dir * SS + s) * BB + b) * G4H;
            g_xp[base + g]     = acc[nt][2] + b0v;
            g_xp[base + g + 1] = acc[nt][3] + b1v;
        }
    }
}

// ---------------------------------------------------------------------------
// Tiled FP32 GEMM (head only)
// ---------------------------------------------------------------------------
__global__ __launch_bounds__(256) void head_gemm_kernel(
    int K, const float* __restrict__ Wf, const float* __restrict__ bf,
    float* __restrict__ out_p)
{
    __shared__ float As[16][132];
    __shared__ float Bs[16][68];

    const float* A = g_ctx;
    const int t  = threadIdx.x;
    const int tx = t & 15;
    const int ty = t >> 4;
    const int m0 = blockIdx.x * 128;
    const int n0 = blockIdx.y * 64;
    const float* Wp = Wf;
    const float* biasp = bf;
    const int wrow0 = n0;

    float acc[8][4];
#pragma unroll
    for (int i = 0; i < 8; i++)
#pragma unroll
        for (int j = 0; j < 4; j++) acc[i][j] = 0.0f;

    const int nkt = K >> 4;
    for (int kt = 0; kt < nkt; kt++) {
        const int k0 = kt << 4;
#pragma unroll
        for (int r = 0; r < 2; r++) {
            int idx = t + r * 256;
            int row = idx >> 2;
            int kq  = idx & 3;
            float4 v = *(const float4*)&A[(size_t)(m0 + row) * K + k0 + kq * 4];
            As[kq * 4 + 0][row] = v.x;
            As[kq * 4 + 1][row] = v.y;
            As[kq * 4 + 2][row] = v.z;
            As[kq * 4 + 3][row] = v.w;
        }
        {
            int row = t >> 2;
            int kq  = t & 3;
            float4 v = *(const float4*)&Wp[(size_t)(wrow0 + row) * K + k0 + kq * 4];
            Bs[kq * 4 + 0][row] = v.x;
            Bs[kq * 4 + 1][row] = v.y;
            Bs[kq * 4 + 2][row] = v.z;
            Bs[kq * 4 + 3][row] = v.w;
        }
        __syncthreads();
#pragma unroll
        for (int kk = 0; kk < 16; kk++) {
            float af[8], bfr[4];
            *(float4*)&af[0]  = *(const float4*)&As[kk][ty * 8];
            *(float4*)&af[4]  = *(const float4*)&As[kk][ty * 8 + 4];
            *(float4*)&bfr[0] = *(const float4*)&Bs[kk][tx * 4];
#pragma unroll
            for (int i = 0; i < 8; i++)
#pragma unroll
                for (int j = 0; j < 4; j++)
                    acc[i][j] = fmaf(af[i], bfr[j], acc[i][j]);
        }
        __syncthreads();
    }

#pragma unroll
    for (int i = 0; i < 8; i++) {
        int m = m0 + ty * 8 + i;
#pragma unroll
        for (int j = 0; j < 4; j++) {
            int c = tx * 4 + j;
            out_p[(size_t)m * 128 + (n0 + c)] = acc[i][j] + biasp[wrow0 + c];
        }
    }
}

// ---------------------------------------------------------------------------
// HMMA bidirectional LSTM layer. 32 CTAs (16/dir), 256 threads (8 warps,
// 2/SMSP). Warp w<4: gate w, ntiles {0,1}; warp w>=4: gate w-4, ntiles {2,3}.
// B-fragments LDG.64 (cg) straight from g_hb (fragment-layout global) — no
// smem staging. A-hi in regs, A-lo in smem. R12 barrier unchanged.
// ---------------------------------------------------------------------------
#define SM_ALO  0             // 32KB: [gate][kt][pair][lane] 8B chunks
#define SM_GATE 32768         // [64 rows][36] floats
#define LSTM_SMEM (32768 + 64 * 36 * 4)

__global__ __launch_bounds__(256, 1) void lstm_mma_kernel(
    const float* __restrict__ whf, const float* __restrict__ whb, int layer)
{
    extern __shared__ char smc[];
    float* GATE = (float*)(smc + SM_GATE);

    const int t     = threadIdx.x;
    const int l     = t & 31;
    const int wid   = t >> 5;             // 0..7
    const int wg    = wid & 3;            // gate
    const int nh    = wid >> 2;           // n-half: 0 -> nt{0,1}, 1 -> nt{2,3}
    const int dir   = blockIdx.x >> 4;
    const int slice = blockIdx.x & 15;
    const float* W  = dir ? whb : whf;
    float* hout     = (layer == 0) ? g_hcat0 : g_hcat1;
    unsigned* bar   = &g_bar[layer * 2 + dir][0];

    const int g  = l >> 2;                // 0..7
    const int tg = l & 3;                 // 0..3
    const int grow0 = wg * 256 + slice * 16 + g;
    const int grow1 = grow0 + 8;

    // ---- one-time: W fragments (hi in regs; lo to smem by warps 0-3) ----
    uint32_t Ahi[16][4];
#pragma unroll
    for (int kt = 0; kt < 16; kt++) {
        int k0 = kt * 16 + tg * 2;
        float2 p00 = *(const float2*)&W[(size_t)grow0 * HH + k0];
        float2 p08 = *(const float2*)&W[(size_t)grow0 * HH + k0 + 8];
        float2 p10 = *(const float2*)&W[(size_t)grow1 * HH + k0];
        float2 p18 = *(const float2*)&W[(size_t)grow1 * HH + k0 + 8];
        float h00x = __bfloat162float(__float2bfloat16(p00.x));
        float h00y = __bfloat162float(__float2bfloat16(p00.y));
        float h08x = __bfloat162float(__float2bfloat16(p08.x));
        float h08y = __bfloat162float(__float2bfloat16(p08.y));
        float h10x = __bfloat162float(__float2bfloat16(p10.x));
        float h10y = __bfloat162float(__float2bfloat16(p10.y));
        float h18x = __bfloat162float(__float2bfloat16(p18.x));
        float h18y = __bfloat162float(__float2bfloat16(p18.y));
        Ahi[kt][0] = pk(h00x, h00y);
        Ahi[kt][1] = pk(h10x, h10y);
        Ahi[kt][2] = pk(h08x, h08y);
        Ahi[kt][3] = pk(h18x, h18y);
        if (wid < 4) {
            uint2 lo1, lo2;
            lo1.x = pk(p00.x - h00x, p00.y - h00y);
            lo1.y = pk(p08.x - h08x, p08.y - h08y);
            lo2.x = pk(p10.x - h10x, p10.y - h10y);
            lo2.y = pk(p18.x - h18x, p18.y - h18y);
            *(uint2*)(smc + SM_ALO + (wg * 16 + kt) * 512 + l * 8)       = lo1;
            *(uint2*)(smc + SM_ALO + (wg * 16 + kt) * 512 + 256 + l * 8) = lo2;
        }
    }

    // activation mapping: u = t>>4 (0..15), batches (t&15)*2 .. +1
    const int au  = t >> 4;
    const int ab0 = (t & 15) * 2;
    const int ug  = slice * 16 + au;
    float cst[2] = {0.f, 0.f};

    // zero parity-0 h stripe (hi+lo)
#pragma unroll
    for (int j = 0; j < 2; j++) {
        uint32_t off = hb_off(ug, ab0 + j);
        *(uint16_t*)(g_hb[dir][0][0] + off) = 0;
        *(uint16_t*)(g_hb[dir][0][1] + off) = 0;
    }

    // phase-1 barrier (init + Alo smem visible)
    unsigned phase = 1;
    __syncthreads();
    if (t == 0) { red_release(bar); wait_ge(bar, 16u * phase); }
    __syncthreads();

    const float* xpd = g_xp + (size_t)dir * SS * BB * G4H;
    const int nt0 = nh * 2;

    for (int s = 0; s < SS; s++) {
        const int p    = s & 1;
        const int tcur = dir ? (SS - 1 - s) : s;

        // prefetch xp for my 4 gates x 2 batches
        float xr[4][2];
        {
            const float* xpb = xpd + (size_t)tcur * BB * G4H;
#pragma unroll
            for (int G = 0; G < 4; G++) {
                int gw = G * 256 + slice * 16 + au;
#pragma unroll
                for (int j = 0; j < 2; j++)
                    xr[G][j] = __ldcg(&xpb[(size_t)(ab0 + j) * G4H + gw]);
            }
        }

        // MMA mainloop: B-frags straight from global (cg), 3-term split
        float acc[2][4];
#pragma unroll
        for (int nt = 0; nt < 2; nt++)
#pragma unroll
            for (int i = 0; i < 4; i++) acc[nt][i] = 0.0f;

        const unsigned char* BH = g_hb[dir][p][0];
        const unsigned char* BL = g_hb[dir][p][1];
#pragma unroll
        for (int kt = 0; kt < 16; kt++) {
            uint2 al1 = *(const uint2*)(smc + SM_ALO + (wg * 16 + kt) * 512 + l * 8);
            uint2 al2 = *(const uint2*)(smc + SM_ALO + (wg * 16 + kt) * 512 + 256 + l * 8);
            uint32_t alo[4] = {al1.x, al2.x, al1.y, al2.y};
#pragma unroll
            for (int q = 0; q < 2; q++) {
                int nt = nt0 + q;
                uint2 bh = ldcg_u2(BH + kt * 1024 + nt * 256 + l * 8);
                uint2 bl = ldcg_u2(BL + kt * 1024 + nt * 256 + l * 8);
                mma_bf16(acc[q], Ahi[kt], (const uint32_t*)&bh);
                mma_bf16(acc[q], alo,     (const uint32_t*)&bh);
                mma_bf16(acc[q], Ahi[kt], (const uint32_t*)&bl);
            }
        }

        // epilogue: D -> GATE smem [row m][n]
        {
            float* gb = GATE + (size_t)(wg * 16 + g) * 36;
#pragma unroll
            for (int q = 0; q < 2; q++) {
                int nt = nt0 + q;
                *(float2*)(gb + nt * 8 + tg * 2)          = make_float2(acc[q][0], acc[q][1]);
                *(float2*)(gb + 8 * 36 + nt * 8 + tg * 2) = make_float2(acc[q][2], acc[q][3]);
            }
        }
        __syncthreads();

        // activation
        {
            unsigned char* thb = g_hb[dir][p ^ 1][0];
            unsigned char* tlb = g_hb[dir][p ^ 1][1];
#pragma unroll
            for (int j = 0; j < 2; j++) {
                int b = ab0 + j;
                float gi = GATE[(size_t)(0 * 16 + au) * 36 + b] + xr[0][j];
                float gf = GATE[(size_t)(1 * 16 + au) * 36 + b] + xr[1][j];
                float gg = GATE[(size_t)(2 * 16 + au) * 36 + b] + xr[2][j];
                float go = GATE[(size_t)(3 * 16 + au) * 36 + b] + xr[3][j];
                float c = sigf(gf) * cst[j] + sigf(gi) * tanhfast(gg);
                cst[j] = c;
                float hv = sigf(go) * tanhfast(c);
                __nv_bfloat16 hh = __float2bfloat16(hv);
                __nv_bfloat16 hl = __float2bfloat16(hv - __bfloat162float(hh));
                uint32_t off = hb_off(ug, b);
                *(__nv_bfloat16*)(thb + off) = hh;
                *(__nv_bfloat16*)(tlb + off) = hl;
                hout[((size_t)b * SS + tcur) * HCAT + dir * HH + ug] = hv;
            }
        }

        if (s == SS - 1) break;

        // per-direction counter barrier (16 arrivals, red.release)
        phase++;
        __syncthreads();
        if (t == 0) { red_release(bar); wait_ge(bar, 16u * phase); }
        __syncthreads();
    }
}

// ---------------------------------------------------------------------------
// attention score: s[b,t] = dot(h[b,t,:], attn_w) + attn_b ; per-b max
// ---------------------------------------------------------------------------
__global__ __launch_bounds__(256) void score_kernel(
    const float* __restrict__ attn_w, const float* __restrict__ attn_b)
{
    __shared__ float aw[HCAT];
    __shared__ float red[8];
    const int b = blockIdx.x;
    const int t = threadIdx.x;
    const int w = t >> 5, l = t & 31;
    for (int j = t; j < HCAT; j += 256) aw[j] = attn_w[j];
    __syncthreads();

    const float ab = attn_b[0];
    float mloc = -1e30f;
    for (int tt = w; tt < SS; tt += 8) {
        const float* hp = g_hcat1 + ((size_t)b * SS + tt) * HCAT;
        float sum = 0.f;
        for (int j = l; j < HCAT; j += 32) sum = fmaf(hp[j], aw[j], sum);
#pragma unroll
        for (int o = 16; o > 0; o >>= 1) sum += __shfl_xor_sync(0xFFFFFFFFu, sum, o);
        float sv = sum + ab;
        if (l == 0) g_s[b * SS + tt] = sv;
        mloc = fmaxf(mloc, sv);
    }
    if (l == 0) red[w] = mloc;
    __syncthreads();
    if (t == 0) {
        float m = red[0];
#pragma unroll
        for (int i = 1; i < 8; i++) m = fmaxf(m, red[i]);
        g_mx[b] = m;
    }
}

// ---------------------------------------------------------------------------
// cumulative softmax context: ctx[b,t,:] = cumsum(e*h)/cumsum(e)
// ---------------------------------------------------------------------------
__global__ __launch_bounds__(512) void ctx_kernel()
{
    const int b = blockIdx.x;
    const int j = threadIdx.x;
    const float mx = g_mx[b];
    float num = 0.f, den = 0.f;
    const float* sb = g_s + b * SS;
#pragma unroll 4
    for (int t = 0; t < SS; t++) {
        float e = __expf(sb[t] - mx);
        den += e;
        size_t off = ((size_t)b * SS + t) * HCAT + j;
        num = fmaf(e, __ldg(&g_hcat1[off]), num);
        g_ctx[off] = __fdividef(num, den);
    }
}

// ---------------------------------------------------------------------------
extern "C" void kernel_launch(void* const* d_in, const int* in_sizes, int n_in,
                              void* d_out, int out_size)
{
    const float* x        = (const float*)d_in[0];
    const float* w_ih_l0f = (const float*)d_in[1];
    const float* w_hh_l0f = (const float*)d_in[2];
    const float* b_l0f    = (const float*)d_in[3];
    const float* w_ih_l0b = (const float*)d_in[4];
    const float* w_hh_l0b = (const float*)d_in[5];
    const float* b_l0b    = (const float*)d_in[6];
    const float* w_ih_l1f = (const float*)d_in[7];
    const float* w_hh_l1f = (const float*)d_in[8];
    const float* b_l1f    = (const float*)d_in[9];
    const float* w_ih_l1b = (const float*)d_in[10];
    const float* w_hh_l1b = (const float*)d_in[11];
    const float* b_l1b    = (const float*)d_in[12];
    const float* attn_w   = (const float*)d_in[13];
    const float* attn_b   = (const float*)d_in[14];
    const float* head_w   = (const float*)d_in[15];
    const float* head_b   = (const float*)d_in[16];
    float* out = (float*)d_out;

    cudaFuncSetAttribute(lstm_mma_kernel, cudaFuncAttributeMaxDynamicSharedMemorySize, LSTM_SMEM);

    reset_kernel<<<1, 128>>>();                                   // idx 0

    // layer 0: bf16 HMMA projection + recurrence (lstm0 in ncu slot 3)
    proj_mma_kernel<0><<<dim3(512, 32), 128>>>(x, DIN, w_ih_l0f, w_ih_l0b, b_l0f, b_l0b);   // idx 1
    dummy_kernel<<<1, 32>>>();                                    // idx 2
    lstm_mma_kernel<<<32, 256, LSTM_SMEM>>>(w_hh_l0f, w_hh_l0b, 0);  // idx 3 <- profiled
    // layer 1: bf16 HMMA projection + recurrence
    proj_mma_kernel<1><<<dim3(512, 32), 128>>>(nullptr, HCAT, w_ih_l1f, w_ih_l1b, b_l1f, b_l1b);
    lstm_mma_kernel<<<32, 256, LSTM_SMEM>>>(w_hh_l1f, w_hh_l1b, 1);

    // attention + context + head
    score_kernel<<<32, 256>>>(attn_w, attn_b);
    ctx_kernel<<<32, 512>>>();
    head_gemm_kernel<<<dim3(256, 2), 256>>>(HCAT, head_w, head_b, out);
}

// round 16
// speedup vs baseline: 2.0913x; 1.0194x over previous
#include <cuda_runtime.h>
#include <cuda_bf16.h>
#include <math.h>
#include <cstdint>

// Problem constants
#define BB 32
#define SS 1024
#define DIN 128
#define HH 256
#define G4H 1024          // 4*H
#define HCAT 512          // 2*H

typedef unsigned long long ull;

// ---------------- scratch (device globals; no cudaMalloc allowed) ----------
__device__ float g_xp[2u * SS * BB * G4H];        // [dir][s][b][4H]
__device__ float g_hcat0[(size_t)BB * SS * HCAT]; // [b][s][512]
__device__ float g_hcat1[(size_t)BB * SS * HCAT];
__device__ float g_ctx[(size_t)BB * SS * HCAT];
__device__ float g_hT[2u * SS * HH * BB];         // [dir][s][u][b] (compact hout)
__device__ unsigned char g_hb[2][2][2][16384];    // [dir][parity][hi/lo][B-frag tile]
__device__ float g_s[BB * SS];
__device__ float g_mx[BB];
__device__ unsigned g_bar[4][32];                 // [layer*2+dir][pad] one line each

// ---------------------------------------------------------------------------
__device__ __forceinline__ float sigf(float x) { return 1.0f / (1.0f + __expf(-x)); }
__device__ __forceinline__ float tanhfast(float x) { return 1.0f - 2.0f / (__expf(2.0f * x) + 1.0f); }

__device__ __forceinline__ unsigned ld_acq(const unsigned* p) {
    unsigned v;
    asm volatile("ld.acquire.gpu.u32 %0, [%1];" : "=r"(v) : "l"(p));
    return v;
}
__device__ __forceinline__ void red_release(unsigned* p) {
    asm volatile("red.release.gpu.global.add.u32 [%0], %1;" :: "l"(p), "r"(1u) : "memory");
}
__device__ __forceinline__ void wait_ge(unsigned* p, unsigned target) {
    int hot = 2048;
    while (ld_acq(p) < target) {
        if (--hot < 0) __nanosleep(256);
    }
}

// m16n8k16 bf16 mma, D=C in-place (fp32 accum)
__device__ __forceinline__ void mma_bf16(float* c, const uint32_t* a, const uint32_t* b) {
    asm("mma.sync.aligned.m16n8k16.row.col.f32.bf16.bf16.f32 "
        "{%0,%1,%2,%3}, {%4,%5,%6,%7}, {%8,%9}, {%0,%1,%2,%3};"
        : "+f"(c[0]), "+f"(c[1]), "+f"(c[2]), "+f"(c[3])
        : "r"(a[0]), "r"(a[1]), "r"(a[2]), "r"(a[3]), "r"(b[0]), "r"(b[1]));
}

__device__ __forceinline__ uint32_t pk(float x, float y) {
    __nv_bfloat162 t = __floats2bfloat162_rn(x, y);
    return *(uint32_t*)&t;
}
// byte offset of h[ug][n] (bf16) inside a 16KB B-frag tile (R12 layout)
__device__ __forceinline__ uint32_t hb_off(int ug, int n) {
    int kt = ug >> 4, rem = ug & 15, low = rem & 1, k2r = rem >> 1;
    int tg = (k2r < 4) ? k2r : (k2r - 4);
    int off4 = (k2r < 4) ? 0 : 4;
    return (uint32_t)(kt * 1024 + n * 32 + tg * 8 + off4 + low * 2);
}

__device__ __forceinline__ uint2 ldcg_u2(const void* p) {
    uint2 v;
    asm volatile("ld.global.cg.v2.u32 {%0,%1}, [%2];" : "=r"(v.x), "=r"(v.y) : "l"(p));
    return v;
}
__device__ __forceinline__ void stcg_u4(void* p, uint4 v) {
    asm volatile("st.global.cg.v4.u32 [%0], {%1,%2,%3,%4};"
                 :: "l"(p), "r"(v.x), "r"(v.y), "r"(v.z), "r"(v.w) : "memory");
}

__global__ void reset_kernel() {
    ((unsigned*)g_bar)[threadIdx.x] = 0u;   // 128 words
}
__global__ void dummy_kernel() {}

// ---------------------------------------------------------------------------
// bf16 HMMA projection GEMM (R14, unchanged): g_xp = A.W^T + bias
// ---------------------------------------------------------------------------
template <int SRC>
__global__ __launch_bounds__(128) void proj_mma_kernel(
    const float* __restrict__ A_in, int KD,
    const float* __restrict__ Wf, const float* __restrict__ Wb,
    const float* __restrict__ bf, const float* __restrict__ bb)
{
    __shared__ char sm[16384];     // AH 4K | AL 4K | BH 4K | BL 4K

    const float* A = (SRC == 0) ? A_in : g_hcat0;
    const int t = threadIdx.x;
    const int l = t & 31;
    const int w = t >> 5;
    const int m0 = blockIdx.x * 64;
    const int n0 = blockIdx.y * 64;

    const float* Wp;
    const float* biasp;
    int wrow0;
    if (n0 < 1024) { Wp = Wf; biasp = bf; wrow0 = n0; }
    else           { Wp = Wb; biasp = bb; wrow0 = n0 - 1024; }

    float acc[8][4];
#pragma unroll
    for (int nt = 0; nt < 8; nt++)
#pragma unroll
        for (int i = 0; i < 4; i++) acc[nt][i] = 0.0f;

    const int niter = KD >> 5;
    for (int it = 0; it < niter; it++) {
        const int k0 = it << 5;
#pragma unroll
        for (int ee = 0; ee < 8; ee++) {
            int e = t + ee * 128;
            int r = e >> 4, p = e & 15;
            float2 v = *(const float2*)&A[(size_t)(m0 + r) * KD + k0 + 2 * p];
            float hx = __bfloat162float(__float2bfloat16(v.x));
            float hy = __bfloat162float(__float2bfloat16(v.y));
            uint32_t hi = pk(hx, hy);
            uint32_t lo = pk(v.x - hx, v.y - hy);
            int rr = r & 15;
            uint32_t off = (uint32_t)((r >> 4) * 2 + (p >> 3)) * 512
                         + (uint32_t)((rr & 7) * 4 + (p & 3)) * 16
                         + (uint32_t)((rr >> 3) + ((p >> 2) & 1) * 2) * 4;
            *(uint32_t*)(sm + off)        = hi;
            *(uint32_t*)(sm + 4096 + off) = lo;
        }
#pragma unroll
        for (int ee = 0; ee < 8; ee++) {
            int e = t + ee * 128;
            int c = e >> 4, p = e & 15;
            float2 v = *(const float2*)&Wp[(size_t)(wrow0 + c) * KD + k0 + 2 * p];
            float hx = __bfloat162float(__float2bfloat16(v.x));
            float hy = __bfloat162float(__float2bfloat16(v.y));
            uint32_t hi = pk(hx, hy);
            uint32_t lo = pk(v.x - hx, v.y - hy);
            uint32_t off = (uint32_t)(p >> 3) * 2048
                         + (uint32_t)(c >> 3) * 256
                         + (uint32_t)((c & 7) * 4 + (p & 3)) * 8
                         + (uint32_t)((p >> 2) & 1) * 4;
            *(uint32_t*)(sm + 8192 + off)  = hi;
            *(uint32_t*)(sm + 12288 + off) = lo;
        }
        __syncthreads();
#pragma unroll
        for (int kt = 0; kt < 2; kt++) {
            uint4 ah = *(const uint4*)(sm + (w * 2 + kt) * 512 + l * 16);
            uint4 al = *(const uint4*)(sm + 4096 + (w * 2 + kt) * 512 + l * 16);
#pragma unroll
            for (int nt = 0; nt < 8; nt++) {
                uint2 bh = *(const uint2*)(sm + 8192 + kt * 2048 + nt * 256 + l * 8);
                uint2 bl = *(const uint2*)(sm + 12288 + kt * 2048 + nt * 256 + l * 8);
                mma_bf16(acc[nt], (const uint32_t*)&ah, (const uint32_t*)&bh);
                mma_bf16(acc[nt], (const uint32_t*)&al, (const uint32_t*)&bh);
                mma_bf16(acc[nt], (const uint32_t*)&ah, (const uint32_t*)&bl);
            }
        }
        __syncthreads();
    }

    const int r0 = m0 + w * 16 + (l >> 2);
#pragma unroll
    for (int nt = 0; nt < 8; nt++) {
        int cl = wrow0 + nt * 8 + (l & 3) * 2;
        float b0v = biasp[cl];
        float b1v = biasp[cl + 1];
        int ng  = n0 + nt * 8 + (l & 3) * 2;
        int dir = ng >> 10;
        int g   = ng & 1023;
        {
            int m = r0, b = m >> 10, s = m & 1023;
            size_t base = ((size_t)(dir * SS + s) * BB + b) * G4H;
            g_xp[base + g]     = acc[nt][0] + b0v;
            g_xp[base + g + 1] = acc[nt][1] + b1v;
        }
        {
            int m = r0 + 8, b = m >> 10, s = m & 1023;
            size_t base = ((size_t)(dir * SS + s) * BB + b) * G4H;
            g_xp[base + g]     = acc[nt][2] + b0v;
            g_xp[base + g + 1] = acc[nt][3] + b1v;
        }
    }
}

// ---------------------------------------------------------------------------
// Transpose g_hT[dir][s][u][b] -> hcat[b][s][dir*256+u]
// ---------------------------------------------------------------------------
__global__ __launch_bounds__(256) void transpose_h_kernel(float* __restrict__ hcat)
{
    __shared__ float tile[32][33];
    const int u0  = blockIdx.x * 32;
    const int s   = blockIdx.y;
    const int dir = blockIdx.z;
    const int t   = threadIdx.x;
    const float* src = g_hT + (size_t)(dir * SS + s) * HH * BB;
#pragma unroll
    for (int k = 0; k < 4; k++) {
        int idx = t + k * 256;
        int up = idx >> 5, b = idx & 31;
        tile[up][b] = src[(size_t)(u0 + up) * BB + b];
    }
    __syncthreads();
#pragma unroll
    for (int k = 0; k < 4; k++) {
        int idx = t + k * 256;
        int b = idx >> 5, up = idx & 31;
        hcat[((size_t)b * SS + s) * HCAT + dir * HH + u0 + up] = tile[up][b];
    }
}

// ---------------------------------------------------------------------------
// Tiled FP32 GEMM (head only)
// ---------------------------------------------------------------------------
__global__ __launch_bounds__(256) void head_gemm_kernel(
    int K, const float* __restrict__ Wf, const float* __restrict__ bf,
    float* __restrict__ out_p)
{
    __shared__ float As[16][132];
    __shared__ float Bs[16][68];

    const float* A = g_ctx;
    const int t  = threadIdx.x;
    const int tx = t & 15;
    const int ty = t >> 4;
    const int m0 = blockIdx.x * 128;
    const int n0 = blockIdx.y * 64;
    const float* Wp = Wf;
    const float* biasp = bf;
    const int wrow0 = n0;

    float acc[8][4];
#pragma unroll
    for (int i = 0; i < 8; i++)
#pragma unroll
        for (int j = 0; j < 4; j++) acc[i][j] = 0.0f;

    const int nkt = K >> 4;
    for (int kt = 0; kt < nkt; kt++) {
        const int k0 = kt << 4;
#pragma unroll
        for (int r = 0; r < 2; r++) {
            int idx = t + r * 256;
            int row = idx >> 2;
            int kq  = idx & 3;
            float4 v = *(const float4*)&A[(size_t)(m0 + row) * K + k0 + kq * 4];
            As[kq * 4 + 0][row] = v.x;
            As[kq * 4 + 1][row] = v.y;
            As[kq * 4 + 2][row] = v.z;
            As[kq * 4 + 3][row] = v.w;
        }
        {
            int row = t >> 2;
            int kq  = t & 3;
            float4 v = *(const float4*)&Wp[(size_t)(wrow0 + row) * K + k0 + kq * 4];
            Bs[kq * 4 + 0][row] = v.x;
            Bs[kq * 4 + 1][row] = v.y;
            Bs[kq * 4 + 2][row] = v.z;
            Bs[kq * 4 + 3][row] = v.w;
        }
        __syncthreads();
#pragma unroll
        for (int kk = 0; kk < 16; kk++) {
            float af[8], bfr[4];
            *(float4*)&af[0]  = *(const float4*)&As[kk][ty * 8];
            *(float4*)&af[4]  = *(const float4*)&As[kk][ty * 8 + 4];
            *(float4*)&bfr[0] = *(const float4*)&Bs[kk][tx * 4];
#pragma unroll
            for (int i = 0; i < 8; i++)
#pragma unroll
                for (int j = 0; j < 4; j++)
                    acc[i][j] = fmaf(af[i], bfr[j], acc[i][j]);
        }
        __syncthreads();
    }

#pragma unroll
    for (int i = 0; i < 8; i++) {
        int m = m0 + ty * 8 + i;
#pragma unroll
        for (int j = 0; j < 4; j++) {
            int c = tx * 4 + j;
            out_p[(size_t)m * 128 + (n0 + c)] = acc[i][j] + biasp[wrow0 + c];
        }
    }
}

// ---------------------------------------------------------------------------
// HMMA bidirectional LSTM layer. 32 CTAs (16/dir), 256 threads (8 warps).
// R15 mainloop; NEW: h-fragment stores go through a 2KB smem repack buffer
// then out as coalesced STG.128; hout goes to compact g_hT (coalesced),
// transposed to g_hcat by a separate kernel. Shrinks the pre-release drain.
// ---------------------------------------------------------------------------
#define SM_ALO  0             // 32KB: [gate][kt][pair][lane] 8B chunks
#define SM_GATE 32768         // [64 rows][36] floats = 9216B
#define SM_HBUF 41984         // 2KB: hi 1K | lo 1K (fragment-layout repack)
#define LSTM_SMEM (41984 + 2048)

__global__ __launch_bounds__(256, 1) void lstm_mma_kernel(
    const float* __restrict__ whf, const float* __restrict__ whb, int layer)
{
    extern __shared__ char smc[];
    float* GATE = (float*)(smc + SM_GATE);

    const int t     = threadIdx.x;
    const int l     = t & 31;
    const int wid   = t >> 5;             // 0..7
    const int wg    = wid & 3;            // gate
    const int nh    = wid >> 2;           // n-half
    const int dir   = blockIdx.x >> 4;
    const int slice = blockIdx.x & 15;
    const float* W  = dir ? whb : whf;
    unsigned* bar   = &g_bar[layer * 2 + dir][0];

    const int g  = l >> 2;
    const int tg = l & 3;
    const int grow0 = wg * 256 + slice * 16 + g;
    const int grow1 = grow0 + 8;

    // ---- one-time: W fragments (hi in regs; lo to smem by warps 0-3) ----
    uint32_t Ahi[16][4];
#pragma unroll
    for (int kt = 0; kt < 16; kt++) {
        int k0 = kt * 16 + tg * 2;
        float2 p00 = *(const float2*)&W[(size_t)grow0 * HH + k0];
        float2 p08 = *(const float2*)&W[(size_t)grow0 * HH + k0 + 8];
        float2 p10 = *(const float2*)&W[(size_t)grow1 * HH + k0];
        float2 p18 = *(const float2*)&W[(size_t)grow1 * HH + k0 + 8];
        float h00x = __bfloat162float(__float2bfloat16(p00.x));
        float h00y = __bfloat162float(__float2bfloat16(p00.y));
        float h08x = __bfloat162float(__float2bfloat16(p08.x));
        float h08y = __bfloat162float(__float2bfloat16(p08.y));
        float h10x = __bfloat162float(__float2bfloat16(p10.x));
        float h10y = __bfloat162float(__float2bfloat16(p10.y));
        float h18x = __bfloat162float(__float2bfloat16(p18.x));
        float h18y = __bfloat162float(__float2bfloat16(p18.y));
        Ahi[kt][0] = pk(h00x, h00y);
        Ahi[kt][1] = pk(h10x, h10y);
        Ahi[kt][2] = pk(h08x, h08y);
        Ahi[kt][3] = pk(h18x, h18y);
        if (wid < 4) {
            uint2 lo1, lo2;
            lo1.x = pk(p00.x - h00x, p00.y - h00y);
            lo1.y = pk(p08.x - h08x, p08.y - h08y);
            lo2.x = pk(p10.x - h10x, p10.y - h10y);
            lo2.y = pk(p18.x - h18x, p18.y - h18y);
            *(uint2*)(smc + SM_ALO + (wg * 16 + kt) * 512 + l * 8)       = lo1;
            *(uint2*)(smc + SM_ALO + (wg * 16 + kt) * 512 + 256 + l * 8) = lo2;
        }
    }

    // activation mapping: u = t>>4 (0..15), batches (t&15)*2 .. +1
    const int au  = t >> 4;
    const int ab0 = (t & 15) * 2;
    const int ug  = slice * 16 + au;
    float cst[2] = {0.f, 0.f};

    // zero parity-0 h stripe (hi+lo) — startup only
#pragma unroll
    for (int j = 0; j < 2; j++) {
        uint32_t off = hb_off(ug, ab0 + j);
        *(uint16_t*)(g_hb[dir][0][0] + off) = 0;
        *(uint16_t*)(g_hb[dir][0][1] + off) = 0;
    }

    // phase-1 barrier (init + Alo smem visible)
    unsigned phase = 1;
    __syncthreads();
    if (t == 0) { red_release(bar); wait_ge(bar, 16u * phase); }
    __syncthreads();

    const float* xpd = g_xp + (size_t)dir * SS * BB * G4H;
    const int nt0 = nh * 2;

    for (int s = 0; s < SS; s++) {
        const int p    = s & 1;
        const int tcur = dir ? (SS - 1 - s) : s;

        // prefetch xp for my 4 gates x 2 batches
        float xr[4][2];
        {
            const float* xpb = xpd + (size_t)tcur * BB * G4H;
#pragma unroll
            for (int G = 0; G < 4; G++) {
                int gw = G * 256 + slice * 16 + au;
#pragma unroll
                for (int j = 0; j < 2; j++)
                    xr[G][j] = __ldcg(&xpb[(size_t)(ab0 + j) * G4H + gw]);
            }
        }

        // MMA mainloop: B-frags straight from global (cg), 3-term split
        float acc[2][4];
#pragma unroll
        for (int nt = 0; nt < 2; nt++)
#pragma unroll
            for (int i = 0; i < 4; i++) acc[nt][i] = 0.0f;

        const unsigned char* BH = g_hb[dir][p][0];
        const unsigned char* BL = g_hb[dir][p][1];
#pragma unroll
        for (int kt = 0; kt < 16; kt++) {
            uint2 al1 = *(const uint2*)(smc + SM_ALO + (wg * 16 + kt) * 512 + l * 8);
            uint2 al2 = *(const uint2*)(smc + SM_ALO + (wg * 16 + kt) * 512 + 256 + l * 8);
            uint32_t alo[4] = {al1.x, al2.x, al1.y, al2.y};
#pragma unroll
            for (int q = 0; q < 2; q++) {
                int nt = nt0 + q;
                uint2 bh = ldcg_u2(BH + kt * 1024 + nt * 256 + l * 8);
                uint2 bl = ldcg_u2(BL + kt * 1024 + nt * 256 + l * 8);
                mma_bf16(acc[q], Ahi[kt], (const uint32_t*)&bh);
                mma_bf16(acc[q], alo,     (const uint32_t*)&bh);
                mma_bf16(acc[q], Ahi[kt], (const uint32_t*)&bl);
            }
        }

        // epilogue: D -> GATE smem [row m][n]
        {
            float* gb = GATE + (size_t)(wg * 16 + g) * 36;
#pragma unroll
            for (int q = 0; q < 2; q++) {
                int nt = nt0 + q;
                *(float2*)(gb + nt * 8 + tg * 2)          = make_float2(acc[q][0], acc[q][1]);
                *(float2*)(gb + 8 * 36 + nt * 8 + tg * 2) = make_float2(acc[q][2], acc[q][3]);
            }
        }
        __syncthreads();

        // activation: write smem hbuf (fragment layout) + compact hout (g_hT)
        {
            unsigned char* hb_hi = (unsigned char*)(smc + SM_HBUF);
            unsigned char* hb_lo = (unsigned char*)(smc + SM_HBUF + 1024);
            float hv2[2];
#pragma unroll
            for (int j = 0; j < 2; j++) {
                int b = ab0 + j;
                float gi = GATE[(size_t)(0 * 16 + au) * 36 + b] + xr[0][j];
                float gf = GATE[(size_t)(1 * 16 + au) * 36 + b] + xr[1][j];
                float gg = GATE[(size_t)(2 * 16 + au) * 36 + b] + xr[2][j];
                float go = GATE[(size_t)(3 * 16 + au) * 36 + b] + xr[3][j];
                float c = sigf(gf) * cst[j] + sigf(gi) * tanhfast(gg);
                cst[j] = c;
                float hv = sigf(go) * tanhfast(c);
                hv2[j] = hv;
                __nv_bfloat16 hh = __float2bfloat16(hv);
                __nv_bfloat16 hl = __float2bfloat16(hv - __bfloat162float(hh));
                uint32_t loff = hb_off(ug, b) - (uint32_t)slice * 1024u;
                *(__nv_bfloat16*)(hb_hi + loff) = hh;
                *(__nv_bfloat16*)(hb_lo + loff) = hl;
            }
            // compact coalesced hout (2 x 128B rows per warp)
            *(float2*)&g_hT[((size_t)(dir * SS + tcur) * HH + ug) * BB + ab0] =
                make_float2(hv2[0], hv2[1]);
        }
        __syncthreads();

        // coalesced copy: smem hbuf -> g_hb slice (128 x STG.128)
        if (t < 128) {
            int hl2 = t >> 6, idx = t & 63;
            uint4 v = *(const uint4*)(smc + SM_HBUF + hl2 * 1024 + idx * 16);
            stcg_u4(g_hb[dir][p ^ 1][hl2] + slice * 1024 + idx * 16, v);
        }

        if (s == SS - 1) break;

        // per-direction counter barrier (16 arrivals, red.release)
        phase++;
        __syncthreads();
        if (t == 0) { red_release(bar); wait_ge(bar, 16u * phase); }
        __syncthreads();
    }
}

// ---------------------------------------------------------------------------
// attention score: s[b,t] = dot(h[b,t,:], attn_w) + attn_b ; per-b max
// ---------------------------------------------------------------------------
__global__ __launch_bounds__(256) void score_kernel(
    const float* __restrict__ attn_w, const float* __restrict__ attn_b)
{
    __shared__ float aw[HCAT];
    __shared__ float red[8];
    const int b = blockIdx.x;
    const int t = threadIdx.x;
    const int w = t >> 5, l = t & 31;
    for (int j = t; j < HCAT; j += 256) aw[j] = attn_w[j];
    __syncthreads();

    const float ab = attn_b[0];
    float mloc = -1e30f;
    for (int tt = w; tt < SS; tt += 8) {
        const float* hp = g_hcat1 + ((size_t)b * SS + tt) * HCAT;
        float sum = 0.f;
        for (int j = l; j < HCAT; j += 32) sum = fmaf(hp[j], aw[j], sum);
#pragma unroll
        for (int o = 16; o > 0; o >>= 1) sum += __shfl_xor_sync(0xFFFFFFFFu, sum, o);
        float sv = sum + ab;
        if (l == 0) g_s[b * SS + tt] = sv;
        mloc = fmaxf(mloc, sv);
    }
    if (l == 0) red[w] = mloc;
    __syncthreads();
    if (t == 0) {
        float m = red[0];
#pragma unroll
        for (int i = 1; i < 8; i++) m = fmaxf(m, red[i]);
        g_mx[b] = m;
    }
}

// ---------------------------------------------------------------------------
// cumulative softmax context: ctx[b,t,:] = cumsum(e*h)/cumsum(e)
// ---------------------------------------------------------------------------
__global__ __launch_bounds__(512) void ctx_kernel()
{
    const int b = blockIdx.x;
    const int j = threadIdx.x;
    const float mx = g_mx[b];
    float num = 0.f, den = 0.f;
    const float* sb = g_s + b * SS;
#pragma unroll 4
    for (int t = 0; t < SS; t++) {
        float e = __expf(sb[t] - mx);
        den += e;
        size_t off = ((size_t)b * SS + t) * HCAT + j;
        num = fmaf(e, __ldg(&g_hcat1[off]), num);
        g_ctx[off] = __fdividef(num, den);
    }
}

// ---------------------------------------------------------------------------
extern "C" void kernel_launch(void* const* d_in, const int* in_sizes, int n_in,
                              void* d_out, int out_size)
{
    const float* x        = (const float*)d_in[0];
    const float* w_ih_l0f = (const float*)d_in[1];
    const float* w_hh_l0f = (const float*)d_in[2];
    const float* b_l0f    = (const float*)d_in[3];
    const float* w_ih_l0b = (const float*)d_in[4];
    const float* w_hh_l0b = (const float*)d_in[5];
    const float* b_l0b    = (const float*)d_in[6];
    const float* w_ih_l1f = (const float*)d_in[7];
    const float* w_hh_l1f = (const float*)d_in[8];
    const float* b_l1f    = (const float*)d_in[9];
    const float* w_ih_l1b = (const float*)d_in[10];
    const float* w_hh_l1b = (const float*)d_in[11];
    const float* b_l1b    = (const float*)d_in[12];
    const float* attn_w   = (const float*)d_in[13];
    const float* attn_b   = (const float*)d_in[14];
    const float* head_w   = (const float*)d_in[15];
    const float* head_b   = (const float*)d_in[16];
    float* out = (float*)d_out;

    // resolve device-global addresses for hcat buffers
    float* hcat0_p = nullptr;
    float* hcat1_p = nullptr;
    cudaGetSymbolAddress((void**)&hcat0_p, g_hcat0);
    cudaGetSymbolAddress((void**)&hcat1_p, g_hcat1);

    cudaFuncSetAttribute(lstm_mma_kernel, cudaFuncAttributeMaxDynamicSharedMemorySize, LSTM_SMEM);

    reset_kernel<<<1, 128>>>();                                   // idx 0

    // layer 0: bf16 HMMA projection + recurrence (lstm0 in ncu slot 3)
    proj_mma_kernel<0><<<dim3(512, 32), 128>>>(x, DIN, w_ih_l0f, w_ih_l0b, b_l0f, b_l0b);   // idx 1
    dummy_kernel<<<1, 32>>>();                                    // idx 2
    lstm_mma_kernel<<<32, 256, LSTM_SMEM>>>(w_hh_l0f, w_hh_l0b, 0);  // idx 3 <- profiled
    transpose_h_kernel<<<dim3(8, 1024, 2), 256>>>(hcat0_p);
    // layer 1: bf16 HMMA projection + recurrence
    proj_mma_kernel<1><<<dim3(512, 32), 128>>>(nullptr, HCAT, w_ih_l1f, w_ih_l1b, b_l1f, b_l1b);
    lstm_mma_kernel<<<32, 256, LSTM_SMEM>>>(w_hh_l1f, w_hh_l1b, 1);
    transpose_h_kernel<<<dim3(8, 1024, 2), 256>>>(hcat1_p);

    // attention + context + head
    score_kernel<<<32, 256>>>(attn_w, attn_b);
    ctx_kernel<<<32, 512>>>();
    head_gemm_kernel<<<dim3(256, 2), 256>>>(HCAT, head_w, head_b, out);
}

// round 17
// speedup vs baseline: 2.2359x; 1.0692x over previous
#include <cuda_runtime.h>
#include <cuda_bf16.h>
#include <math.h>
#include <cstdint>

// Problem constants
#define BB 32
#define SS 1024
#define DIN 128
#define HH 256
#define G4H 1024          // 4*H
#define HCAT 512          // 2*H

typedef unsigned long long ull;

// ---------------- scratch (device globals; no cudaMalloc allowed) ----------
__device__ float g_xp[2u * SS * BB * G4H];        // [dir][s][b][4H]
__device__ float g_hcat0[(size_t)BB * SS * HCAT]; // [b][s][512]
__device__ float g_hcat1[(size_t)BB * SS * HCAT];
__device__ float g_ctx[(size_t)BB * SS * HCAT];
__device__ float g_hT[2u * SS * HH * BB];         // [dir][s][u][b] (compact hout)
__device__ unsigned char g_hb[2][2][32768];       // [dir][parity][interleaved hi/lo B-frag tile]
__device__ float g_s[BB * SS];
__device__ float g_mx[BB];
__device__ unsigned g_bar[4][32];                 // [layer*2+dir][pad] one line each

// ---------------------------------------------------------------------------
__device__ __forceinline__ float sigf(float x) { return 1.0f / (1.0f + __expf(-x)); }
__device__ __forceinline__ float tanhfast(float x) { return 1.0f - 2.0f / (__expf(2.0f * x) + 1.0f); }

__device__ __forceinline__ unsigned ld_acq(const unsigned* p) {
    unsigned v;
    asm volatile("ld.acquire.gpu.u32 %0, [%1];" : "=r"(v) : "l"(p));
    return v;
}
__device__ __forceinline__ void red_release(unsigned* p) {
    asm volatile("red.release.gpu.global.add.u32 [%0], %1;" :: "l"(p), "r"(1u) : "memory");
}
__device__ __forceinline__ void wait_ge(unsigned* p, unsigned target) {
    int hot = 2048;
    while (ld_acq(p) < target) {
        if (--hot < 0) __nanosleep(256);
    }
}

// m16n8k16 bf16 mma, D=C in-place (fp32 accum)
__device__ __forceinline__ void mma_bf16(float* c, const uint32_t* a, const uint32_t* b) {
    asm("mma.sync.aligned.m16n8k16.row.col.f32.bf16.bf16.f32 "
        "{%0,%1,%2,%3}, {%4,%5,%6,%7}, {%8,%9}, {%0,%1,%2,%3};"
        : "+f"(c[0]), "+f"(c[1]), "+f"(c[2]), "+f"(c[3])
        : "r"(a[0]), "r"(a[1]), "r"(a[2]), "r"(a[3]), "r"(b[0]), "r"(b[1]));
}

__device__ __forceinline__ uint32_t pk(float x, float y) {
    __nv_bfloat162 t = __floats2bfloat162_rn(x, y);
    return *(uint32_t*)&t;
}

__device__ __forceinline__ uint4 ldcg_u4(const void* p) {
    uint4 v;
    asm volatile("ld.global.cg.v4.u32 {%0,%1,%2,%3}, [%4];"
                 : "=r"(v.x), "=r"(v.y), "=r"(v.z), "=r"(v.w) : "l"(p));
    return v;
}
__device__ __forceinline__ void stcg_u4(void* p, uint4 v) {
    asm volatile("st.global.cg.v4.u32 [%0], {%1,%2,%3,%4};"
                 :: "l"(p), "r"(v.x), "r"(v.y), "r"(v.z), "r"(v.w) : "memory");
}

__global__ void reset_kernel() {
    ((unsigned*)g_bar)[threadIdx.x] = 0u;   // 128 words
}
__global__ void dummy_kernel() {}

// ---------------------------------------------------------------------------
// bf16 HMMA projection GEMM (R14, unchanged): g_xp = A.W^T + bias
// ---------------------------------------------------------------------------
template <int SRC>
__global__ __launch_bounds__(128) void proj_mma_kernel(
    const float* __restrict__ A_in, int KD,
    const float* __restrict__ Wf, const float* __restrict__ Wb,
    const float* __restrict__ bf, const float* __restrict__ bb)
{
    __shared__ char sm[16384];     // AH 4K | AL 4K | BH 4K | BL 4K

    const float* A = (SRC == 0) ? A_in : g_hcat0;
    const int t = threadIdx.x;
    const int l = t & 31;
    const int w = t >> 5;
    const int m0 = blockIdx.x * 64;
    const int n0 = blockIdx.y * 64;

    const float* Wp;
    const float* biasp;
    int wrow0;
    if (n0 < 1024) { Wp = Wf; biasp = bf; wrow0 = n0; }
    else           { Wp = Wb; biasp = bb; wrow0 = n0 - 1024; }

    float acc[8][4];
#pragma unroll
    for (int nt = 0; nt < 8; nt++)
#pragma unroll
        for (int i = 0; i < 4; i++) acc[nt][i] = 0.0f;

    const int niter = KD >> 5;
    for (int it = 0; it < niter; it++) {
        const int k0 = it << 5;
#pragma unroll
        for (int ee = 0; ee < 8; ee++) {
            int e = t + ee * 128;
            int r = e >> 4, p = e & 15;
            float2 v = *(const float2*)&A[(size_t)(m0 + r) * KD + k0 + 2 * p];
            float hx = __bfloat162float(__float2bfloat16(v.x));
            float hy = __bfloat162float(__float2bfloat16(v.y));
            uint32_t hi = pk(hx, hy);
            uint32_t lo = pk(v.x - hx, v.y - hy);
            int rr = r & 15;
            uint32_t off = (uint32_t)((r >> 4) * 2 + (p >> 3)) * 512
                         + (uint32_t)((rr & 7) * 4 + (p & 3)) * 16
                         + (uint32_t)((rr >> 3) + ((p >> 2) & 1) * 2) * 4;
            *(uint32_t*)(sm + off)        = hi;
            *(uint32_t*)(sm + 4096 + off) = lo;
        }
#pragma unroll
        for (int ee = 0; ee < 8; ee++) {
            int e = t + ee * 128;
            int c = e >> 4, p = e & 15;
            float2 v = *(const float2*)&Wp[(size_t)(wrow0 + c) * KD + k0 + 2 * p];
            float hx = __bfloat162float(__float2bfloat16(v.x));
            float hy = __bfloat162float(__float2bfloat16(v.y));
            uint32_t hi = pk(hx, hy);
            uint32_t lo = pk(v.x - hx, v.y - hy);
            uint32_t off = (uint32_t)(p >> 3) * 2048
                         + (uint32_t)(c >> 3) * 256
                         + (uint32_t)((c & 7) * 4 + (p & 3)) * 8
                         + (uint32_t)((p >> 2) & 1) * 4;
            *(uint32_t*)(sm + 8192 + off)  = hi;
            *(uint32_t*)(sm + 12288 + off) = lo;
        }
        __syncthreads();
#pragma unroll
        for (int kt = 0; kt < 2; kt++) {
            uint4 ah = *(const uint4*)(sm + (w * 2 + kt) * 512 + l * 16);
            uint4 al = *(const uint4*)(sm + 4096 + (w * 2 + kt) * 512 + l * 16);
#pragma unroll
            for (int nt = 0; nt < 8; nt++) {
                uint2 bh = *(const uint2*)(sm + 8192 + kt * 2048 + nt * 256 + l * 8);
                uint2 bl = *(const uint2*)(sm + 12288 + kt * 2048 + nt * 256 + l * 8);
                mma_bf16(acc[nt], (const uint32_t*)&ah, (const uint32_t*)&bh);
                mma_bf16(acc[nt], (const uint32_t*)&al, (const uint32_t*)&bh);
                mma_bf16(acc[nt], (const uint32_t*)&ah, (const uint32_t*)&bl);
            }
        }
        __syncthreads();
    }

    const int r0 = m0 + w * 16 + (l >> 2);
#pragma unroll
    for (int nt = 0; nt < 8; nt++) {
        int cl = wrow0 + nt * 8 + (l & 3) * 2;
        float b0v = biasp[cl];
        float b1v = biasp[cl + 1];
        int ng  = n0 + nt * 8 + (l & 3) * 2;
        int dir = ng >> 10;
        int g   = ng & 1023;
        {
            int m = r0, b = m >> 10, s = m & 1023;
            size_t base = ((size_t)(dir * SS + s) * BB + b) * G4H;
            g_xp[base + g]     = acc[nt][0] + b0v;
            g_xp[base + g + 1] = acc[nt][1] + b1v;
        }
        {
            int m = r0 + 8, b = m >> 10, s = m & 1023;
            size_t base = ((size_t)(dir * SS + s) * BB + b) * G4H;
            g_xp[base + g]     = acc[nt][2] + b0v;
            g_xp[base + g + 1] = acc[nt][3] + b1v;
        }
    }
}

// ---------------------------------------------------------------------------
// Transpose g_hT[dir][s][u][b] -> hcat[b][s][dir*256+u]
// ---------------------------------------------------------------------------
__global__ __launch_bounds__(256) void transpose_h_kernel(float* __restrict__ hcat)
{
    __shared__ float tile[32][33];
    const int u0  = blockIdx.x * 32;
    const int s   = blockIdx.y;
    const int dir = blockIdx.z;
    const int t   = threadIdx.x;
    const float* src = g_hT + (size_t)(dir * SS + s) * HH * BB;
#pragma unroll
    for (int k = 0; k < 4; k++) {
        int idx = t + k * 256;
        int up = idx >> 5, b = idx & 31;
        tile[up][b] = src[(size_t)(u0 + up) * BB + b];
    }
    __syncthreads();
#pragma unroll
    for (int k = 0; k < 4; k++) {
        int idx = t + k * 256;
        int b = idx >> 5, up = idx & 31;
        hcat[((size_t)b * SS + s) * HCAT + dir * HH + u0 + up] = tile[up][b];
    }
}

// ---------------------------------------------------------------------------
// Tiled FP32 GEMM (head only)
// ---------------------------------------------------------------------------
__global__ __launch_bounds__(256) void head_gemm_kernel(
    int K, const float* __restrict__ Wf, const float* __restrict__ bf,
    float* __restrict__ out_p)
{
    __shared__ float As[16][132];
    __shared__ float Bs[16][68];

    const float* A = g_ctx;
    const int t  = threadIdx.x;
    const int tx = t & 15;
    const int ty = t >> 4;
    const int m0 = blockIdx.x * 128;
    const int n0 = blockIdx.y * 64;
    const float* Wp = Wf;
    const float* biasp = bf;
    const int wrow0 = n0;

    float acc[8][4];
#pragma unroll
    for (int i = 0; i < 8; i++)
#pragma unroll
        for (int j = 0; j < 4; j++) acc[i][j] = 0.0f;

    const int nkt = K >> 4;
    for (int kt = 0; kt < nkt; kt++) {
        const int k0 = kt << 4;
#pragma unroll
        for (int r = 0; r < 2; r++) {
            int idx = t + r * 256;
            int row = idx >> 2;
            int kq  = idx & 3;
            float4 v = *(const float4*)&A[(size_t)(m0 + row) * K + k0 + kq * 4];
            As[kq * 4 + 0][row] = v.x;
            As[kq * 4 + 1][row] = v.y;
            As[kq * 4 + 2][row] = v.z;
            As[kq * 4 + 3][row] = v.w;
        }
        {
            int row = t >> 2;
            int kq  = t & 3;
            float4 v = *(const float4*)&Wp[(size_t)(wrow0 + row) * K + k0 + kq * 4];
            Bs[kq * 4 + 0][row] = v.x;
            Bs[kq * 4 + 1][row] = v.y;
            Bs[kq * 4 + 2][row] = v.z;
            Bs[kq * 4 + 3][row] = v.w;
        }
        __syncthreads();
#pragma unroll
        for (int kk = 0; kk < 16; kk++) {
            float af[8], bfr[4];
            *(float4*)&af[0]  = *(const float4*)&As[kk][ty * 8];
            *(float4*)&af[4]  = *(const float4*)&As[kk][ty * 8 + 4];
            *(float4*)&bfr[0] = *(const float4*)&Bs[kk][tx * 4];
#pragma unroll
            for (int i = 0; i < 8; i++)
#pragma unroll
                for (int j = 0; j < 4; j++)
                    acc[i][j] = fmaf(af[i], bfr[j], acc[i][j]);
        }
        __syncthreads();
    }

#pragma unroll
    for (int i = 0; i < 8; i++) {
        int m = m0 + ty * 8 + i;
#pragma unroll
        for (int j = 0; j < 4; j++) {
            int c = tx * 4 + j;
            out_p[(size_t)m * 128 + (n0 + c)] = acc[i][j] + biasp[wrow0 + c];
        }
    }
}

// ---------------------------------------------------------------------------
// HMMA bidirectional LSTM layer. 32 CTAs (16/dir), 256 threads (8 warps).
// hi/lo B-fragments interleaved in 16B chunks -> 32 LDG.128/warp mainloop.
// h repack via contiguous 2KB smem slice -> 128 coalesced STG.128.
// Barrier wake: per-warp-leader acquire poll + __syncwarp.
// ---------------------------------------------------------------------------
#define SM_ALO  0             // 32KB: [gate][kt][pair][lane] 8B chunks
#define SM_GATE 32768         // [64 rows][36] floats = 9216B
#define SM_HBUF 41984         // 2KB: interleaved-fragment slice repack
#define LSTM_SMEM (41984 + 2048)

__global__ __launch_bounds__(256, 1) void lstm_mma_kernel(
    const float* __restrict__ whf, const float* __restrict__ whb, int layer)
{
    extern __shared__ char smc[];
    float* GATE = (float*)(smc + SM_GATE);

    const int t     = threadIdx.x;
    const int l     = t & 31;
    const int wid   = t >> 5;             // 0..7
    const int wg    = wid & 3;            // gate
    const int nh    = wid >> 2;           // n-half
    const int dir   = blockIdx.x >> 4;
    const int slice = blockIdx.x & 15;
    const float* W  = dir ? whb : whf;
    unsigned* bar   = &g_bar[layer * 2 + dir][0];

    const int g  = l >> 2;
    const int tg = l & 3;
    const int grow0 = wg * 256 + slice * 16 + g;
    const int grow1 = grow0 + 8;

    // ---- one-time: W fragments (hi in regs; lo to smem by warps 0-3) ----
    uint32_t Ahi[16][4];
#pragma unroll
    for (int kt = 0; kt < 16; kt++) {
        int k0 = kt * 16 + tg * 2;
        float2 p00 = *(const float2*)&W[(size_t)grow0 * HH + k0];
        float2 p08 = *(const float2*)&W[(size_t)grow0 * HH + k0 + 8];
        float2 p10 = *(const float2*)&W[(size_t)grow1 * HH + k0];
        float2 p18 = *(const float2*)&W[(size_t)grow1 * HH + k0 + 8];
        float h00x = __bfloat162float(__float2bfloat16(p00.x));
        float h00y = __bfloat162float(__float2bfloat16(p00.y));
        float h08x = __bfloat162float(__float2bfloat16(p08.x));
        float h08y = __bfloat162float(__float2bfloat16(p08.y));
        float h10x = __bfloat162float(__float2bfloat16(p10.x));
        float h10y = __bfloat162float(__float2bfloat16(p10.y));
        float h18x = __bfloat162float(__float2bfloat16(p18.x));
        float h18y = __bfloat162float(__float2bfloat16(p18.y));
        Ahi[kt][0] = pk(h00x, h00y);
        Ahi[kt][1] = pk(h10x, h10y);
        Ahi[kt][2] = pk(h08x, h08y);
        Ahi[kt][3] = pk(h18x, h18y);
        if (wid < 4) {
            uint2 lo1, lo2;
            lo1.x = pk(p00.x - h00x, p00.y - h00y);
            lo1.y = pk(p08.x - h08x, p08.y - h08y);
            lo2.x = pk(p10.x - h10x, p10.y - h10y);
            lo2.y = pk(p18.x - h18x, p18.y - h18y);
            *(uint2*)(smc + SM_ALO + (wg * 16 + kt) * 512 + l * 8)       = lo1;
            *(uint2*)(smc + SM_ALO + (wg * 16 + kt) * 512 + 256 + l * 8) = lo2;
        }
    }

    // activation mapping: u = t>>4 (0..15), batches (t&15)*2 .. +1
    const int au  = t >> 4;
    const int ab0 = (t & 15) * 2;
    const int ug  = slice * 16 + au;
    float cst[2] = {0.f, 0.f};

    // activation fragment offsets within the CTA's 2KB slice (interleaved 16B)
    // chunk = nt*512 + lfr*16 ; hi at +off4+low*2, lo at +8+off4+low*2
    const int rem  = ug & 15;
    const int low  = rem & 1;
    const int k2r  = rem >> 1;
    const int atg  = (k2r < 4) ? k2r : (k2r - 4);
    const int off4 = (k2r < 4) ? 0 : 4;

    // zero parity-0 slice (interleaved hi+lo) — startup only
    if (t < 128) stcg_u4(g_hb[dir][0] + slice * 2048 + t * 16, make_uint4(0, 0, 0, 0));

    // phase-1 barrier (init + Alo smem visible)
    unsigned phase = 1;
    __syncthreads();
    if (t == 0) { red_release(bar); wait_ge(bar, 16u * phase); }
    __syncthreads();

    const float* xpd = g_xp + (size_t)dir * SS * BB * G4H;
    const int nt0 = nh * 2;

    for (int s = 0; s < SS; s++) {
        const int p    = s & 1;
        const int tcur = dir ? (SS - 1 - s) : s;

        // prefetch xp for my 4 gates x 2 batches
        float xr[4][2];
        {
            const float* xpb = xpd + (size_t)tcur * BB * G4H;
#pragma unroll
            for (int G = 0; G < 4; G++) {
                int gw = G * 256 + slice * 16 + au;
#pragma unroll
                for (int j = 0; j < 2; j++)
                    xr[G][j] = __ldcg(&xpb[(size_t)(ab0 + j) * G4H + gw]);
            }
        }

        // MMA mainloop: interleaved B-frags, one LDG.128 per (kt, nt)
        float acc[2][4];
#pragma unroll
        for (int nt = 0; nt < 2; nt++)
#pragma unroll
            for (int i = 0; i < 4; i++) acc[nt][i] = 0.0f;

        const unsigned char* BT = g_hb[dir][p];
#pragma unroll
        for (int kt = 0; kt < 16; kt++) {
            uint2 al1 = *(const uint2*)(smc + SM_ALO + (wg * 16 + kt) * 512 + l * 8);
            uint2 al2 = *(const uint2*)(smc + SM_ALO + (wg * 16 + kt) * 512 + 256 + l * 8);
            uint32_t alo[4] = {al1.x, al2.x, al1.y, al2.y};
#pragma unroll
            for (int q = 0; q < 2; q++) {
                int nt = nt0 + q;
                uint4 bb = ldcg_u4(BT + kt * 2048 + nt * 512 + l * 16);
                uint32_t bh[2] = {bb.x, bb.y};
                uint32_t bl[2] = {bb.z, bb.w};
                mma_bf16(acc[q], Ahi[kt], bh);
                mma_bf16(acc[q], alo,     bh);
                mma_bf16(acc[q], Ahi[kt], bl);
            }
        }

        // epilogue: D -> GATE smem [row m][n]
        {
            float* gb = GATE + (size_t)(wg * 16 + g) * 36;
#pragma unroll
            for (int q = 0; q < 2; q++) {
                int nt = nt0 + q;
                *(float2*)(gb + nt * 8 + tg * 2)          = make_float2(acc[q][0], acc[q][1]);
                *(float2*)(gb + 8 * 36 + nt * 8 + tg * 2) = make_float2(acc[q][2], acc[q][3]);
            }
        }
        __syncthreads();

        // activation: write interleaved smem slice + compact hout (g_hT)
        {
            unsigned char* hb = (unsigned char*)(smc + SM_HBUF);
            float hv2[2];
#pragma unroll
            for (int j = 0; j < 2; j++) {
                int b = ab0 + j;
                float gi = GATE[(size_t)(0 * 16 + au) * 36 + b] + xr[0][j];
                float gf = GATE[(size_t)(1 * 16 + au) * 36 + b] + xr[1][j];
                float gg = GATE[(size_t)(2 * 16 + au) * 36 + b] + xr[2][j];
                float go = GATE[(size_t)(3 * 16 + au) * 36 + b] + xr[3][j];
                float c = sigf(gf) * cst[j] + sigf(gi) * tanhfast(gg);
                cst[j] = c;
                float hv = sigf(go) * tanhfast(c);
                hv2[j] = hv;
                __nv_bfloat16 hh = __float2bfloat16(hv);
                __nv_bfloat16 hl = __float2bfloat16(hv - __bfloat162float(hh));
                int nt  = b >> 3;
                int lfr = (b & 7) * 4 + atg;
                uint32_t base = (uint32_t)(nt * 512 + lfr * 16 + off4 + low * 2);
                *(__nv_bfloat16*)(hb + base)     = hh;
                *(__nv_bfloat16*)(hb + base + 8) = hl;
            }
            // compact coalesced hout (2 x 128B rows per warp)
            *(float2*)&g_hT[((size_t)(dir * SS + tcur) * HH + ug) * BB + ab0] =
                make_float2(hv2[0], hv2[1]);
        }
        __syncthreads();

        // coalesced copy: smem slice -> g_hb (128 x STG.128, contiguous 2KB)
        if (t < 128) {
            uint4 v = *(const uint4*)(smc + SM_HBUF + t * 16);
            stcg_u4(g_hb[dir][p ^ 1] + slice * 2048 + t * 16, v);
        }

        if (s == SS - 1) break;

        // per-direction counter barrier: arrival sync + t0 release,
        // per-warp-leader acquire poll + syncwarp wake
        phase++;
        __syncthreads();
        if (t == 0) red_release(bar);
        if (l == 0) wait_ge(bar, 16u * phase);
        __syncwarp();
    }
}

// ---------------------------------------------------------------------------
// attention score: s[b,t] = dot(h[b,t,:], attn_w) + attn_b ; per-b max
// ---------------------------------------------------------------------------
__global__ __launch_bounds__(256) void score_kernel(
    const float* __restrict__ attn_w, const float* __restrict__ attn_b)
{
    __shared__ float aw[HCAT];
    __shared__ float red[8];
    const int b = blockIdx.x;
    const int t = threadIdx.x;
    const int w = t >> 5, l = t & 31;
    for (int j = t; j < HCAT; j += 256) aw[j] = attn_w[j];
    __syncthreads();

    const float ab = attn_b[0];
    float mloc = -1e30f;
    for (int tt = w; tt < SS; tt += 8) {
        const float* hp = g_hcat1 + ((size_t)b * SS + tt) * HCAT;
        float sum = 0.f;
        for (int j = l; j < HCAT; j += 32) sum = fmaf(hp[j], aw[j], sum);
#pragma unroll
        for (int o = 16; o > 0; o >>= 1) sum += __shfl_xor_sync(0xFFFFFFFFu, sum, o);
        float sv = sum + ab;
        if (l == 0) g_s[b * SS + tt] = sv;
        mloc = fmaxf(mloc, sv);
    }
    if (l == 0) red[w] = mloc;
    __syncthreads();
    if (t == 0) {
        float m = red[0];
#pragma unroll
        for (int i = 1; i < 8; i++) m = fmaxf(m, red[i]);
        g_mx[b] = m;
    }
}

// ---------------------------------------------------------------------------
// cumulative softmax context: ctx[b,t,:] = cumsum(e*h)/cumsum(e)
// ---------------------------------------------------------------------------
__global__ __launch_bounds__(512) void ctx_kernel()
{
    const int b = blockIdx.x;
    const int j = threadIdx.x;
    const float mx = g_mx[b];
    float num = 0.f, den = 0.f;
    const float* sb = g_s + b * SS;
#pragma unroll 4
    for (int t = 0; t < SS; t++) {
        float e = __expf(sb[t] - mx);
        den += e;
        size_t off = ((size_t)b * SS + t) * HCAT + j;
        num = fmaf(e, __ldg(&g_hcat1[off]), num);
        g_ctx[off] = __fdividef(num, den);
    }
}

// ---------------------------------------------------------------------------
extern "C" void kernel_launch(void* const* d_in, const int* in_sizes, int n_in,
                              void* d_out, int out_size)
{
    const float* x        = (const float*)d_in[0];
    const float* w_ih_l0f = (const float*)d_in[1];
    const float* w_hh_l0f = (const float*)d_in[2];
    const float* b_l0f    = (const float*)d_in[3];
    const float* w_ih_l0b = (const float*)d_in[4];
    const float* w_hh_l0b = (const float*)d_in[5];
    const float* b_l0b    = (const float*)d_in[6];
    const float* w_ih_l1f = (const float*)d_in[7];
    const float* w_hh_l1f = (const float*)d_in[8];
    const float* b_l1f    = (const float*)d_in[9];
    const float* w_ih_l1b = (const float*)d_in[10];
    const float* w_hh_l1b = (const float*)d_in[11];
    const float* b_l1b    = (const float*)d_in[12];
    const float* attn_w   = (const float*)d_in[13];
    const float* attn_b   = (const float*)d_in[14];
    const float* head_w   = (const float*)d_in[15];
    const float* head_b   = (const float*)d_in[16];
    float* out = (float*)d_out;

    // resolve device-global addresses for hcat buffers
    float* hcat0_p = nullptr;
    float* hcat1_p = nullptr;
    cudaGetSymbolAddress((void**)&hcat0_p, g_hcat0);
    cudaGetSymbolAddress((void**)&hcat1_p, g_hcat1);

    cudaFuncSetAttribute(lstm_mma_kernel, cudaFuncAttributeMaxDynamicSharedMemorySize, LSTM_SMEM);

    reset_kernel<<<1, 128>>>();                                   // idx 0

    // layer 0: bf16 HMMA projection + recurrence (lstm0 in ncu slot 3)
    proj_mma_kernel<0><<<dim3(512, 32), 128>>>(x, DIN, w_ih_l0f, w_ih_l0b, b_l0f, b_l0b);   // idx 1
    dummy_kernel<<<1, 32>>>();                                    // idx 2
    lstm_mma_kernel<<<32, 256, LSTM_SMEM>>>(w_hh_l0f, w_hh_l0b, 0);  // idx 3 <- profiled
    transpose_h_kernel<<<dim3(8, 1024, 2), 256>>>(hcat0_p);
    // layer 1: bf16 HMMA projection + recurrence
    proj_mma_kernel<1><<<dim3(512, 32), 128>>>(nullptr, HCAT, w_ih_l1f, w_ih_l1b, b_l1f, b_l1b);
    lstm_mma_kernel<<<32, 256, LSTM_SMEM>>>(w_hh_l1f, w_hh_l1b, 1);
    transpose_h_kernel<<<dim3(8, 1024, 2), 256>>>(hcat1_p);

    // attention + context + head
    score_kernel<<<32, 256>>>(attn_w, attn_b);
    ctx_kernel<<<32, 512>>>();
    head_gemm_kernel<<<dim3(256, 2), 256>>>(HCAT, head_w, head_b, out);
}